// round 11
// baseline (speedup 1.0000x reference)
#include <cuda_runtime.h>
#include <cuda_fp16.h>
#include <math.h>
#include <stdint.h>

// Problem constants (fixed shapes)
#define BSZ     4
#define LSEQ    2048
#define DMODEL  1024
#define DSTATE  16
#define DCONV   4
#define DINNER  2048
#define MTOK    (BSZ * LSEQ)            // 8192 tokens
#define CHUNK   128
#define NCH     (LSEQ / CHUNK)          // 16 chunks

// ---------------------------------------------------------------------------
// Static device scratch (no cudaMalloc allowed)
// ---------------------------------------------------------------------------
__device__ float  g_xz[(size_t)MTOK * 2 * DINNER];          // (8192, 4096) fp32
__device__ __half g_xh[(size_t)MTOK * DMODEL];              // x rounded fp16
__device__ __half g_WinT_hi[(size_t)2 * DINNER * DMODEL];   // W_in^T hi (4096,1024)
__device__ __half g_WinT_lo[(size_t)2 * DINNER * DMODEL];   // W_in^T lo
__device__ __half g_WoutT_hi[(size_t)DMODEL * DINNER];      // W_out^T hi (1024,2048)
__device__ __half g_WoutT_lo[(size_t)DMODEL * DINNER];
__device__ __half g_yh[(size_t)MTOK * DINNER];              // scan output fp16
__device__ float  g_cs[(size_t)BSZ * NCH * DSTATE * DINNER];// chunk states, 8 MB

// ---------------------------------------------------------------------------
// PTX helpers (sm_80+ only: ldmatrix / mma.sync / cp.async)
// ---------------------------------------------------------------------------
__device__ __forceinline__ uint32_t smem_u32(const void* p) {
    uint32_t a;
    asm("{ .reg .u64 t; cvta.to.shared.u64 t, %1; cvt.u32.u64 %0, t; }"
        : "=r"(a) : "l"(p));
    return a;
}

__device__ __forceinline__ void ldsm_x4(uint32_t* r, uint32_t addr) {
    asm volatile("ldmatrix.sync.aligned.m8n8.x4.shared.b16 {%0,%1,%2,%3}, [%4];"
                 : "=r"(r[0]), "=r"(r[1]), "=r"(r[2]), "=r"(r[3]) : "r"(addr));
}

// fp32-accumulator mma (carries the O(1) hi-pass signal)
__device__ __forceinline__ void mma_f16(float* c, const uint32_t* a,
                                        uint32_t b0, uint32_t b1) {
    asm volatile(
        "mma.sync.aligned.m16n8k16.row.col.f32.f16.f16.f32 "
        "{%0,%1,%2,%3}, {%4,%5,%6,%7}, {%8,%9}, {%0,%1,%2,%3};"
        : "+f"(c[0]), "+f"(c[1]), "+f"(c[2]), "+f"(c[3])
        : "r"(a[0]), "r"(a[1]), "r"(a[2]), "r"(a[3]), "r"(b0), "r"(b1));
}

// fp16-accumulator mma (2x rate on legacy path; lo-pass sums ~5e-3 << 65504)
__device__ __forceinline__ void mma_f16acc(uint32_t* c, const uint32_t* a,
                                           uint32_t b0, uint32_t b1) {
    asm volatile(
        "mma.sync.aligned.m16n8k16.row.col.f16.f16.f16.f16 "
        "{%0,%1}, {%2,%3,%4,%5}, {%6,%7}, {%0,%1};"
        : "+r"(c[0]), "+r"(c[1])
        : "r"(a[0]), "r"(a[1]), "r"(a[2]), "r"(a[3]), "r"(b0), "r"(b1));
}

__device__ __forceinline__ void cp_async16(uint32_t saddr, const void* gptr) {
    asm volatile("cp.async.cg.shared.global [%0], [%1], 16;"
                 :: "r"(saddr), "l"(gptr));
}
#define CP_COMMIT() asm volatile("cp.async.commit_group;" ::: "memory")
#define CP_WAIT(n)  asm volatile("cp.async.wait_group %0;" :: "n"(n) : "memory")

// ---------------------------------------------------------------------------
// fp16 2-pass split GEMM:  C[M,N] = A[M,K] @ B[N,K]^T  (fp32 out)
//   A: fp16-rounded [M,K];  B: fp16 hi/lo split [N,K].
//   hi pass (A*Bhi): fp32 accumulator.  lo pass (A*Blo): fp16 accumulator
//   (Ootomo correction-term trick; added to fp32 in the epilogue).
// CTA 128x128, BK=64, 512 threads (16 warps, 4x4, 32x32 warp tiles).
// 3-stage cp.async ring (48KB/stage), ONE __syncthreads per k-tile.
// SW128 swizzle: 16B chunk index ^= (row & 7).
// ---------------------------------------------------------------------------
__global__ __launch_bounds__(512, 1) void gemm_f16x2(
    int M, int N, int K,
    const __half* __restrict__ Ah,
    const __half* __restrict__ Bhi,
    const __half* __restrict__ Blo,
    float* __restrict__ C)
{
    constexpr int TILE_B = 128 * 128;         // 16KB per operand tile
    constexpr int STAGE_B = TILE_B * 3;       // Ah, Bhi, Blo = 48KB
    constexpr int BK = 64;
    constexpr int NSTAGE = 3;

    extern __shared__ char dsmem_raw[];
    const uint32_t raw_u32 = smem_u32(dsmem_raw);
    const uint32_t base = (raw_u32 + 1023u) & ~1023u;

    const int tid = threadIdx.x;
    const int wid = tid >> 5;
    const int lane = tid & 31;
    const int warpM = wid & 3;
    const int warpN = wid >> 2;
    const int blockRow = blockIdx.y;
    const int blockCol = blockIdx.x;

    const __half* opSrc[3] = { Ah, Bhi, Blo };

    // One 48KB stage: 3 operands x 1024 chunks = 3072, 6 per thread.
    auto loadStageAsync = [&](int stage, int k0) {
        #pragma unroll
        for (int i = 0; i < 6; i++) {
            const int idx = tid + 512 * i;
            const int operand = idx >> 10;        // 0..2
            const int rem = idx & 1023;
            const int row = rem >> 3;             // 0..127
            const int chunk = rem & 7;            // 0..7
            const int gRow = (operand == 0 ? blockRow : blockCol) * 128 + row;
            const __half* src = opSrc[operand] + (size_t)gRow * K + k0 + chunk * 8;
            const uint32_t saddr = base + stage * STAGE_B + operand * TILE_B
                                 + row * 128 + ((chunk ^ (row & 7)) << 4);
            cp_async16(saddr, src);
        }
    };

    float acc[2][4][4];                       // hi-pass fp32 accumulators
    uint32_t lacc[2][4][2];                   // lo-pass fp16x2 accumulators
    #pragma unroll
    for (int m = 0; m < 2; m++)
        #pragma unroll
        for (int n = 0; n < 4; n++) {
            #pragma unroll
            for (int j = 0; j < 4; j++) acc[m][n][j] = 0.0f;
            lacc[m][n][0] = 0u;
            lacc[m][n][1] = 0u;
        }

    const int nK = K / BK;
    loadStageAsync(0, 0);
    CP_COMMIT();
    if (nK > 1) { loadStageAsync(1, BK); CP_COMMIT(); }

    for (int t = 0; t < nK; t++) {
        if (t + 1 < nK) { CP_WAIT(1); } else { CP_WAIT(0); }
        __syncthreads();   // all threads done with compute(t-1) AND see stage t

        if (t + 2 < nK) { loadStageAsync((t + 2) % NSTAGE, (t + 2) * BK); CP_COMMIT(); }

        const uint32_t sbase = base + (t % NSTAGE) * STAGE_B;
        const uint32_t sA  = sbase + 0 * TILE_B;
        const uint32_t sBh = sbase + 1 * TILE_B;
        const uint32_t sBl = sbase + 2 * TILE_B;

        #pragma unroll
        for (int ks = 0; ks < 4; ks++) {
            const int chunk = ks * 2 + (lane >> 4);

            uint32_t afr[2][4];                   // [mtile][regs]
            #pragma unroll
            for (int mt = 0; mt < 2; mt++) {
                const int row = warpM * 32 + mt * 16 + (lane & 15);
                ldsm_x4(afr[mt], sA + row * 128 + ((chunk ^ (row & 7)) << 4));
            }

            uint32_t bfr[2][2][4];                // [hi/lo][npair][regs]
            #pragma unroll
            for (int np = 0; np < 2; np++) {
                const int row = warpN * 32 + np * 16 + (lane & 15);
                const uint32_t off = row * 128 + ((chunk ^ (row & 7)) << 4);
                ldsm_x4(bfr[0][np], sBh + off);
                ldsm_x4(bfr[1][np], sBl + off);
            }

            // hi pass: fp32 acc
            #pragma unroll
            for (int mt = 0; mt < 2; mt++)
                #pragma unroll
                for (int np = 0; np < 2; np++)
                    #pragma unroll
                    for (int h = 0; h < 2; h++)
                        mma_f16(acc[mt][np * 2 + h], afr[mt],
                                bfr[0][np][h], bfr[0][np][h + 2]);
            // lo pass: fp16 acc (2x rate)
            #pragma unroll
            for (int mt = 0; mt < 2; mt++)
                #pragma unroll
                for (int np = 0; np < 2; np++)
                    #pragma unroll
                    for (int h = 0; h < 2; h++)
                        mma_f16acc(lacc[mt][np * 2 + h], afr[mt],
                                   bfr[1][np][h], bfr[1][np][h + 2]);
        }
        // next iteration's single barrier protects the ring slot (dist 2 of 3)
    }

    // Epilogue: fp32 hi + unpacked fp16 lo.
    // f16 C frag: reg0 = {(g, 2t), (g, 2t+1)}, reg1 = {(g+8, 2t), (g+8, 2t+1)}
    const int g = lane >> 2;
    const int tcol = (lane & 3) * 2;
    #pragma unroll
    for (int mt = 0; mt < 2; mt++) {
        const int r0 = blockRow * 128 + warpM * 32 + mt * 16 + g;
        #pragma unroll
        for (int n = 0; n < 4; n++) {
            const int col = blockCol * 128 + warpN * 32 + n * 8 + tcol;
            const __half2 p0 = *reinterpret_cast<const __half2*>(&lacc[mt][n][0]);
            const __half2 p1 = *reinterpret_cast<const __half2*>(&lacc[mt][n][1]);
            float2 v01 = make_float2(acc[mt][n][0] + __low2float(p0),
                                     acc[mt][n][1] + __high2float(p0));
            float2 v23 = make_float2(acc[mt][n][2] + __low2float(p1),
                                     acc[mt][n][3] + __high2float(p1));
            *reinterpret_cast<float2*>(C + (size_t)r0 * N + col) = v01;
            *reinterpret_cast<float2*>(C + (size_t)(r0 + 8) * N + col) = v23;
        }
    }
}

// ---------------------------------------------------------------------------
// Elementwise fp32 -> fp16 round (vectorized).
// ---------------------------------------------------------------------------
__global__ __launch_bounds__(256) void round_f16(
    const float* __restrict__ in, __half* __restrict__ outh, int n4)
{
    const int idx = blockIdx.x * blockDim.x + threadIdx.x;
    if (idx >= n4) return;
    const float4 v = reinterpret_cast<const float4*>(in)[idx];
    __half h[4] = { __float2half(v.x), __float2half(v.y),
                    __float2half(v.z), __float2half(v.w) };
    reinterpret_cast<uint2*>(outh)[idx] = *reinterpret_cast<uint2*>(h);
}

// ---------------------------------------------------------------------------
// Transposed split: W[K,N] fp32 -> Th/Tl[N,K] fp16 hi/lo.
// ---------------------------------------------------------------------------
__global__ __launch_bounds__(256) void transpose_split(
    const float* __restrict__ W,
    __half* __restrict__ Th,
    __half* __restrict__ Tl,
    int K, int N)
{
    __shared__ float tile[32][33];
    const int k0 = blockIdx.y * 32;
    const int n0 = blockIdx.x * 32;
    const int tx = threadIdx.x;
    const int ty = threadIdx.y;

    #pragma unroll
    for (int r = ty; r < 32; r += 8)
        tile[r][tx] = W[(size_t)(k0 + r) * N + n0 + tx];
    __syncthreads();

    #pragma unroll
    for (int r = ty; r < 32; r += 8) {
        const float v = tile[tx][r];
        const __half h = __float2half(v);
        const __half l = __float2half(v - __half2float(h));
        const size_t o = (size_t)(n0 + r) * K + k0 + tx;
        Th[o] = h;
        Tl[o] = l;
    }
}

// ---------------------------------------------------------------------------
// Chunked scan, pass 1: per (b, chunk, d) conv + 128-step scan from zero
// state; write the 16 final states to g_cs.
// ---------------------------------------------------------------------------
__global__ __launch_bounds__(256) void scan_pass1(
    const float* __restrict__ conv_w,
    const float* __restrict__ conv_b,
    const float* __restrict__ A_log)
{
    const int gid = blockIdx.x * blockDim.x + threadIdx.x;
    const int d = gid & (DINNER - 1);
    const int rest = gid >> 11;
    const int c = rest & (NCH - 1);
    const int b = rest >> 4;

    const float* xz = g_xz + (size_t)b * LSEQ * (2 * DINNER);
    const int t0 = c * CHUNK;

    const float w0 = conv_w[d * DCONV + 0];
    const float w1 = conv_w[d * DCONV + 1];
    const float w2 = conv_w[d * DCONV + 2];
    const float w3 = conv_w[d * DCONV + 3];
    const float bias = conv_b[d];

    float Aval[DSTATE];
    #pragma unroll
    for (int s = 0; s < DSTATE; s++)
        Aval[s] = -expf(A_log[s * DINNER + d]);

    float st[DSTATE];
    #pragma unroll
    for (int s = 0; s < DSTATE; s++) st[s] = 0.0f;

    float x0 = 0.f, x1 = 0.f, x2 = 0.f, x3 = 0.f;
    if (c > 0) {
        x1 = xz[(size_t)(t0 - 3) * (2 * DINNER) + d];
        x2 = xz[(size_t)(t0 - 2) * (2 * DINNER) + d];
        x3 = xz[(size_t)(t0 - 1) * (2 * DINNER) + d];
    }

    constexpr int U = 8;
    for (int tt = 0; tt < CHUNK; tt += U) {
        float uv[U];
        #pragma unroll
        for (int i = 0; i < U; i++)
            uv[i] = xz[(size_t)(t0 + tt + i) * (2 * DINNER) + d];
        #pragma unroll
        for (int i = 0; i < U; i++) {
            x0 = x1; x1 = x2; x2 = x3; x3 = uv[i];
            float uc = fmaf(w0, x0, fmaf(w1, x1, fmaf(w2, x2, fmaf(w3, x3, bias))));
            #pragma unroll
            for (int s = 0; s < DSTATE; s++)
                st[s] = fmaf(st[s], Aval[s], uc);
        }
    }

    float* cs = g_cs + ((size_t)(b * NCH + c) * DSTATE) * DINNER + d;
    #pragma unroll
    for (int s = 0; s < DSTATE; s++)
        cs[(size_t)s * DINNER] = st[s];
}

// ---------------------------------------------------------------------------
// Chunked scan, pass 2 (combine): init[0]=0; init[c]=A^128*init[c-1]+lf[c-1]
// ---------------------------------------------------------------------------
__global__ __launch_bounds__(256) void scan_combine(
    const float* __restrict__ A_log)
{
    const int gid = blockIdx.x * blockDim.x + threadIdx.x;
    const int d = gid & (DINNER - 1);
    const int b = gid >> 11;

    float A128[DSTATE];
    #pragma unroll
    for (int s = 0; s < DSTATE; s++)
        A128[s] = expf(128.0f * A_log[s * DINNER + d]);

    float init[DSTATE];
    #pragma unroll
    for (int s = 0; s < DSTATE; s++) init[s] = 0.0f;

    for (int c = 0; c < NCH; c++) {
        float* cs = g_cs + ((size_t)(b * NCH + c) * DSTATE) * DINNER + d;
        float lf[DSTATE];
        #pragma unroll
        for (int s = 0; s < DSTATE; s++) lf[s] = cs[(size_t)s * DINNER];
        #pragma unroll
        for (int s = 0; s < DSTATE; s++) cs[(size_t)s * DINNER] = init[s];
        #pragma unroll
        for (int s = 0; s < DSTATE; s++)
            init[s] = fmaf(A128[s], init[s], lf[s]);
    }
}

// ---------------------------------------------------------------------------
// Chunked scan, pass 3: rescan from correct initial state, D skip + silu
// gate, emit y as single fp16.
// ---------------------------------------------------------------------------
__global__ __launch_bounds__(256) void scan_pass2(
    const float* __restrict__ conv_w,
    const float* __restrict__ conv_b,
    const float* __restrict__ A_log,
    const float* __restrict__ D_param)
{
    const int gid = blockIdx.x * blockDim.x + threadIdx.x;
    const int d = gid & (DINNER - 1);
    const int rest = gid >> 11;
    const int c = rest & (NCH - 1);
    const int b = rest >> 4;

    const float* xz = g_xz + (size_t)b * LSEQ * (2 * DINNER);
    __half* yh = g_yh + (size_t)b * LSEQ * DINNER;
    const int t0 = c * CHUNK;

    const float w0 = conv_w[d * DCONV + 0];
    const float w1 = conv_w[d * DCONV + 1];
    const float w2 = conv_w[d * DCONV + 2];
    const float w3 = conv_w[d * DCONV + 3];
    const float bias = conv_b[d];
    const float Dp = D_param[d];

    float Aval[DSTATE];
    #pragma unroll
    for (int s = 0; s < DSTATE; s++)
        Aval[s] = -expf(A_log[s * DINNER + d]);

    float st[DSTATE];
    {
        const float* cs = g_cs + ((size_t)(b * NCH + c) * DSTATE) * DINNER + d;
        #pragma unroll
        for (int s = 0; s < DSTATE; s++) st[s] = cs[(size_t)s * DINNER];
    }

    float x0 = 0.f, x1 = 0.f, x2 = 0.f, x3 = 0.f;
    if (c > 0) {
        x1 = xz[(size_t)(t0 - 3) * (2 * DINNER) + d];
        x2 = xz[(size_t)(t0 - 2) * (2 * DINNER) + d];
        x3 = xz[(size_t)(t0 - 1) * (2 * DINNER) + d];
    }

    constexpr int U = 8;
    for (int tt = 0; tt < CHUNK; tt += U) {
        float uv[U], zv[U];
        #pragma unroll
        for (int i = 0; i < U; i++) {
            const size_t off = (size_t)(t0 + tt + i) * (2 * DINNER) + d;
            uv[i] = xz[off];
            zv[i] = xz[off + DINNER];
        }
        #pragma unroll
        for (int i = 0; i < U; i++) {
            x0 = x1; x1 = x2; x2 = x3; x3 = uv[i];
            float uc = fmaf(w0, x0, fmaf(w1, x1, fmaf(w2, x2, fmaf(w3, x3, bias))));
            float acc = Dp * uc;
            #pragma unroll
            for (int s = 0; s < DSTATE; s++) {
                st[s] = fmaf(st[s], Aval[s], uc);
                acc += st[s];
            }
            const float z = zv[i];
            const float sig = 1.0f / (1.0f + expf(-z));
            yh[(size_t)(t0 + tt + i) * DINNER + d] = __float2half(acc * (z * sig));
        }
    }
}

// ---------------------------------------------------------------------------
extern "C" void kernel_launch(void* const* d_in, const int* in_sizes, int n_in,
                              void* d_out, int out_size)
{
    const float* x       = (const float*)d_in[0];
    const float* W_in    = (const float*)d_in[1];
    const float* conv_w  = (const float*)d_in[2];
    const float* conv_b  = (const float*)d_in[3];
    const float* A_log   = (const float*)d_in[4];
    const float* D_param = (const float*)d_in[5];
    const float* W_out   = (const float*)d_in[6];
    float* out = (float*)d_out;

    float *xz_p;
    __half *xh_p, *winh_p, *winl_p, *wouth_p, *woutl_p, *yh_p;
    cudaGetSymbolAddress((void**)&xz_p,    g_xz);
    cudaGetSymbolAddress((void**)&xh_p,    g_xh);
    cudaGetSymbolAddress((void**)&winh_p,  g_WinT_hi);
    cudaGetSymbolAddress((void**)&winl_p,  g_WinT_lo);
    cudaGetSymbolAddress((void**)&wouth_p, g_WoutT_hi);
    cudaGetSymbolAddress((void**)&woutl_p, g_WoutT_lo);
    cudaGetSymbolAddress((void**)&yh_p,    g_yh);

    // 3 stages x 48KB + alignment pad (opt-in above 48KB)
    const int GEMM_SMEM = 3 * 3 * 128 * 128 + 1024;
    cudaFuncSetAttribute(gemm_f16x2,
                         cudaFuncAttributeMaxDynamicSharedMemorySize, GEMM_SMEM);

    // 1) Round x to fp16
    {
        const int n4 = MTOK * DMODEL / 4;
        round_f16<<<(n4 + 255) / 256, 256>>>(x, xh_p, n4);
    }
    // 2) Transpose+split weights (fp16 hi/lo)
    {
        dim3 blk(32, 8);
        dim3 g1(2 * DINNER / 32, DMODEL / 32);
        transpose_split<<<g1, blk>>>(W_in, winh_p, winl_p, DMODEL, 2 * DINNER);
        dim3 g2(DMODEL / 32, DINNER / 32);
        transpose_split<<<g2, blk>>>(W_out, wouth_p, woutl_p, DINNER, DMODEL);
    }
    // 3) GEMM1: xz = x @ W_in
    {
        dim3 grid(2 * DINNER / 128, MTOK / 128);
        gemm_f16x2<<<grid, 512, GEMM_SMEM>>>(MTOK, 2 * DINNER, DMODEL,
                                             xh_p, winh_p, winl_p, xz_p);
    }
    // 4) Chunked conv+scan+gate (3 passes)
    scan_pass1 <<<(BSZ * NCH * DINNER) / 256, 256>>>(conv_w, conv_b, A_log);
    scan_combine<<<(BSZ * DINNER) / 256, 256>>>(A_log);
    scan_pass2 <<<(BSZ * NCH * DINNER) / 256, 256>>>(conv_w, conv_b, A_log, D_param);
    // 5) GEMM2: out = y @ W_out
    {
        dim3 grid(DMODEL / 128, MTOK / 128);
        gemm_f16x2<<<grid, 512, GEMM_SMEM>>>(MTOK, DMODEL, DINNER,
                                             yh_p, wouth_p, woutl_p, out);
    }
}

// round 12
// speedup vs baseline: 1.1521x; 1.1521x over previous
#include <cuda_runtime.h>
#include <cuda_fp16.h>
#include <math.h>
#include <stdint.h>

// Problem constants (fixed shapes)
#define BSZ     4
#define LSEQ    2048
#define DMODEL  1024
#define DSTATE  16
#define DCONV   4
#define DINNER  2048
#define MTOK    (BSZ * LSEQ)            // 8192 tokens
#define CHUNK   128
#define NCH     (LSEQ / CHUNK)          // 16 chunks

// ---------------------------------------------------------------------------
// Static device scratch (no cudaMalloc allowed)
// ---------------------------------------------------------------------------
__device__ float  g_xz[(size_t)MTOK * 2 * DINNER];          // (8192, 4096) fp32
__device__ __half g_xh[(size_t)MTOK * DMODEL];              // x rounded fp16
__device__ __half g_WinT_hi[(size_t)2 * DINNER * DMODEL];   // W_in^T hi (4096,1024)
__device__ __half g_WinT_lo[(size_t)2 * DINNER * DMODEL];   // W_in^T lo
__device__ __half g_WoutT_hi[(size_t)DMODEL * DINNER];      // W_out^T hi (1024,2048)
__device__ __half g_WoutT_lo[(size_t)DMODEL * DINNER];      // (unused in 1-pass)
__device__ __half g_yh[(size_t)MTOK * DINNER];              // scan output fp16
__device__ float  g_cs[(size_t)BSZ * NCH * DSTATE * DINNER];// chunk states, 8 MB

// ---------------------------------------------------------------------------
// PTX helpers (sm_80+ only: ldmatrix / mma.sync / cp.async)
// ---------------------------------------------------------------------------
__device__ __forceinline__ uint32_t smem_u32(const void* p) {
    uint32_t a;
    asm("{ .reg .u64 t; cvta.to.shared.u64 t, %1; cvt.u32.u64 %0, t; }"
        : "=r"(a) : "l"(p));
    return a;
}

__device__ __forceinline__ void ldsm_x4(uint32_t* r, uint32_t addr) {
    asm volatile("ldmatrix.sync.aligned.m8n8.x4.shared.b16 {%0,%1,%2,%3}, [%4];"
                 : "=r"(r[0]), "=r"(r[1]), "=r"(r[2]), "=r"(r[3]) : "r"(addr));
}

__device__ __forceinline__ void mma_f16(float* c, const uint32_t* a,
                                        uint32_t b0, uint32_t b1) {
    asm volatile(
        "mma.sync.aligned.m16n8k16.row.col.f32.f16.f16.f32 "
        "{%0,%1,%2,%3}, {%4,%5,%6,%7}, {%8,%9}, {%0,%1,%2,%3};"
        : "+f"(c[0]), "+f"(c[1]), "+f"(c[2]), "+f"(c[3])
        : "r"(a[0]), "r"(a[1]), "r"(a[2]), "r"(a[3]), "r"(b0), "r"(b1));
}

__device__ __forceinline__ void cp_async16(uint32_t saddr, const void* gptr) {
    asm volatile("cp.async.cg.shared.global [%0], [%1], 16;"
                 :: "r"(saddr), "l"(gptr));
}
#define CP_COMMIT() asm volatile("cp.async.commit_group;" ::: "memory")
#define CP_WAIT(n)  asm volatile("cp.async.wait_group %0;" :: "n"(n) : "memory")

// ---------------------------------------------------------------------------
// fp16 split GEMM, NPASS template:  C[M,N] = A[M,K] @ B[N,K]^T  (fp32 out)
//   A: fp16-rounded [M,K].
//   NPASS=2: B split hi/lo, C = A*Bhi + A*Blo (both fp32 acc).
//   NPASS=1: B hi only (W rounding ~2.8e-4 RMS — used where budget allows).
// CTA 128x128, BK=64, 512 threads (16 warps, 4x4, 32x32 warp tiles).
// 3-stage cp.async ring ((1+NPASS)*16KB per stage), ONE barrier per k-tile.
// SW128 swizzle: 16B chunk index ^= (row & 7).
// ---------------------------------------------------------------------------
template <int NPASS>
__global__ __launch_bounds__(512, 1) void gemm_f16(
    int M, int N, int K,
    const __half* __restrict__ Ah,
    const __half* __restrict__ Bhi,
    const __half* __restrict__ Blo,
    float* __restrict__ C)
{
    constexpr int TILE_B = 128 * 128;           // 16KB per operand tile
    constexpr int NOP = 1 + NPASS;              // operands per stage
    constexpr int STAGE_B = TILE_B * NOP;
    constexpr int BK = 64;
    constexpr int NSTAGE = 3;
    constexpr int CHUNKS = NOP * 1024;          // 16B chunks per stage
    constexpr int PER_THR = CHUNKS / 512;

    extern __shared__ char dsmem_raw[];
    const uint32_t raw_u32 = smem_u32(dsmem_raw);
    const uint32_t base = (raw_u32 + 1023u) & ~1023u;

    const int tid = threadIdx.x;
    const int wid = tid >> 5;
    const int lane = tid & 31;
    const int warpM = wid & 3;
    const int warpN = wid >> 2;
    const int blockRow = blockIdx.y;
    const int blockCol = blockIdx.x;

    const __half* opSrc[3] = { Ah, Bhi, Blo };

    auto loadStageAsync = [&](int stage, int k0) {
        #pragma unroll
        for (int i = 0; i < PER_THR; i++) {
            const int idx = tid + 512 * i;
            const int operand = idx >> 10;        // 0..NOP-1
            const int rem = idx & 1023;
            const int row = rem >> 3;             // 0..127
            const int chunk = rem & 7;            // 0..7
            const int gRow = (operand == 0 ? blockRow : blockCol) * 128 + row;
            const __half* src = opSrc[operand] + (size_t)gRow * K + k0 + chunk * 8;
            const uint32_t saddr = base + stage * STAGE_B + operand * TILE_B
                                 + row * 128 + ((chunk ^ (row & 7)) << 4);
            cp_async16(saddr, src);
        }
    };

    float acc[2][4][4];
    #pragma unroll
    for (int m = 0; m < 2; m++)
        #pragma unroll
        for (int n = 0; n < 4; n++)
            #pragma unroll
            for (int j = 0; j < 4; j++) acc[m][n][j] = 0.0f;

    const int nK = K / BK;
    loadStageAsync(0, 0);
    CP_COMMIT();
    if (nK > 1) { loadStageAsync(1, BK); CP_COMMIT(); }

    for (int t = 0; t < nK; t++) {
        if (t + 1 < nK) { CP_WAIT(1); } else { CP_WAIT(0); }
        __syncthreads();   // all threads done with compute(t-1) AND see stage t

        if (t + 2 < nK) { loadStageAsync((t + 2) % NSTAGE, (t + 2) * BK); CP_COMMIT(); }

        const uint32_t sbase = base + (t % NSTAGE) * STAGE_B;
        const uint32_t sA = sbase;

        #pragma unroll
        for (int ks = 0; ks < 4; ks++) {
            const int chunk = ks * 2 + (lane >> 4);

            uint32_t afr[2][4];
            #pragma unroll
            for (int mt = 0; mt < 2; mt++) {
                const int row = warpM * 32 + mt * 16 + (lane & 15);
                ldsm_x4(afr[mt], sA + row * 128 + ((chunk ^ (row & 7)) << 4));
            }

            uint32_t bfr[NPASS][2][4];
            #pragma unroll
            for (int p = 0; p < NPASS; p++)
                #pragma unroll
                for (int np = 0; np < 2; np++) {
                    const int row = warpN * 32 + np * 16 + (lane & 15);
                    const uint32_t off = row * 128 + ((chunk ^ (row & 7)) << 4);
                    ldsm_x4(bfr[p][np], sbase + (1 + p) * TILE_B + off);
                }

            #pragma unroll
            for (int p = 0; p < NPASS; p++)
                #pragma unroll
                for (int mt = 0; mt < 2; mt++)
                    #pragma unroll
                    for (int np = 0; np < 2; np++)
                        #pragma unroll
                        for (int h = 0; h < 2; h++)
                            mma_f16(acc[mt][np * 2 + h], afr[mt],
                                    bfr[p][np][h], bfr[p][np][h + 2]);
        }
        // next iteration's single barrier protects the ring slot (dist 2 of 3)
    }

    const int g = lane >> 2;
    const int tcol = (lane & 3) * 2;
    #pragma unroll
    for (int mt = 0; mt < 2; mt++) {
        const int r0 = blockRow * 128 + warpM * 32 + mt * 16 + g;
        #pragma unroll
        for (int n = 0; n < 4; n++) {
            const int col = blockCol * 128 + warpN * 32 + n * 8 + tcol;
            float2 v01 = make_float2(acc[mt][n][0], acc[mt][n][1]);
            float2 v23 = make_float2(acc[mt][n][2], acc[mt][n][3]);
            *reinterpret_cast<float2*>(C + (size_t)r0 * N + col) = v01;
            *reinterpret_cast<float2*>(C + (size_t)(r0 + 8) * N + col) = v23;
        }
    }
}

// ---------------------------------------------------------------------------
// Elementwise fp32 -> fp16 round (vectorized).
// ---------------------------------------------------------------------------
__global__ __launch_bounds__(256) void round_f16(
    const float* __restrict__ in, __half* __restrict__ outh, int n4)
{
    const int idx = blockIdx.x * blockDim.x + threadIdx.x;
    if (idx >= n4) return;
    const float4 v = reinterpret_cast<const float4*>(in)[idx];
    __half h[4] = { __float2half(v.x), __float2half(v.y),
                    __float2half(v.z), __float2half(v.w) };
    reinterpret_cast<uint2*>(outh)[idx] = *reinterpret_cast<uint2*>(h);
}

// ---------------------------------------------------------------------------
// Transposed split: W[K,N] fp32 -> Th/Tl[N,K] fp16 hi/lo.
// ---------------------------------------------------------------------------
__global__ __launch_bounds__(256) void transpose_split(
    const float* __restrict__ W,
    __half* __restrict__ Th,
    __half* __restrict__ Tl,
    int K, int N)
{
    __shared__ float tile[32][33];
    const int k0 = blockIdx.y * 32;
    const int n0 = blockIdx.x * 32;
    const int tx = threadIdx.x;
    const int ty = threadIdx.y;

    #pragma unroll
    for (int r = ty; r < 32; r += 8)
        tile[r][tx] = W[(size_t)(k0 + r) * N + n0 + tx];
    __syncthreads();

    #pragma unroll
    for (int r = ty; r < 32; r += 8) {
        const float v = tile[tx][r];
        const __half h = __float2half(v);
        const __half l = __float2half(v - __half2float(h));
        const size_t o = (size_t)(n0 + r) * K + k0 + tx;
        Th[o] = h;
        Tl[o] = l;
    }
}

// ---------------------------------------------------------------------------
// Chunked scan, pass 1: per (b, chunk, d) conv + 128-step scan from zero
// state; write the 16 final states to g_cs.
// ---------------------------------------------------------------------------
__global__ __launch_bounds__(256) void scan_pass1(
    const float* __restrict__ conv_w,
    const float* __restrict__ conv_b,
    const float* __restrict__ A_log)
{
    const int gid = blockIdx.x * blockDim.x + threadIdx.x;
    const int d = gid & (DINNER - 1);
    const int rest = gid >> 11;
    const int c = rest & (NCH - 1);
    const int b = rest >> 4;

    const float* xz = g_xz + (size_t)b * LSEQ * (2 * DINNER);
    const int t0 = c * CHUNK;

    const float w0 = conv_w[d * DCONV + 0];
    const float w1 = conv_w[d * DCONV + 1];
    const float w2 = conv_w[d * DCONV + 2];
    const float w3 = conv_w[d * DCONV + 3];
    const float bias = conv_b[d];

    float Aval[DSTATE];
    #pragma unroll
    for (int s = 0; s < DSTATE; s++)
        Aval[s] = -expf(A_log[s * DINNER + d]);

    float st[DSTATE];
    #pragma unroll
    for (int s = 0; s < DSTATE; s++) st[s] = 0.0f;

    float x0 = 0.f, x1 = 0.f, x2 = 0.f, x3 = 0.f;
    if (c > 0) {
        x1 = xz[(size_t)(t0 - 3) * (2 * DINNER) + d];
        x2 = xz[(size_t)(t0 - 2) * (2 * DINNER) + d];
        x3 = xz[(size_t)(t0 - 1) * (2 * DINNER) + d];
    }

    constexpr int U = 8;
    for (int tt = 0; tt < CHUNK; tt += U) {
        float uv[U];
        #pragma unroll
        for (int i = 0; i < U; i++)
            uv[i] = xz[(size_t)(t0 + tt + i) * (2 * DINNER) + d];
        #pragma unroll
        for (int i = 0; i < U; i++) {
            x0 = x1; x1 = x2; x2 = x3; x3 = uv[i];
            float uc = fmaf(w0, x0, fmaf(w1, x1, fmaf(w2, x2, fmaf(w3, x3, bias))));
            #pragma unroll
            for (int s = 0; s < DSTATE; s++)
                st[s] = fmaf(st[s], Aval[s], uc);
        }
    }

    float* cs = g_cs + ((size_t)(b * NCH + c) * DSTATE) * DINNER + d;
    #pragma unroll
    for (int s = 0; s < DSTATE; s++)
        cs[(size_t)s * DINNER] = st[s];
}

// ---------------------------------------------------------------------------
// Chunked scan, pass 2 (combine): init[0]=0; init[c]=A^128*init[c-1]+lf[c-1]
// ---------------------------------------------------------------------------
__global__ __launch_bounds__(256) void scan_combine(
    const float* __restrict__ A_log)
{
    const int gid = blockIdx.x * blockDim.x + threadIdx.x;
    const int d = gid & (DINNER - 1);
    const int b = gid >> 11;

    float A128[DSTATE];
    #pragma unroll
    for (int s = 0; s < DSTATE; s++)
        A128[s] = expf(128.0f * A_log[s * DINNER + d]);

    float init[DSTATE];
    #pragma unroll
    for (int s = 0; s < DSTATE; s++) init[s] = 0.0f;

    for (int c = 0; c < NCH; c++) {
        float* cs = g_cs + ((size_t)(b * NCH + c) * DSTATE) * DINNER + d;
        float lf[DSTATE];
        #pragma unroll
        for (int s = 0; s < DSTATE; s++) lf[s] = cs[(size_t)s * DINNER];
        #pragma unroll
        for (int s = 0; s < DSTATE; s++) cs[(size_t)s * DINNER] = init[s];
        #pragma unroll
        for (int s = 0; s < DSTATE; s++)
            init[s] = fmaf(A128[s], init[s], lf[s]);
    }
}

// ---------------------------------------------------------------------------
// Chunked scan, pass 3: rescan from correct initial state, D skip + silu
// gate, emit y as single fp16.
// ---------------------------------------------------------------------------
__global__ __launch_bounds__(256) void scan_pass2(
    const float* __restrict__ conv_w,
    const float* __restrict__ conv_b,
    const float* __restrict__ A_log,
    const float* __restrict__ D_param)
{
    const int gid = blockIdx.x * blockDim.x + threadIdx.x;
    const int d = gid & (DINNER - 1);
    const int rest = gid >> 11;
    const int c = rest & (NCH - 1);
    const int b = rest >> 4;

    const float* xz = g_xz + (size_t)b * LSEQ * (2 * DINNER);
    __half* yh = g_yh + (size_t)b * LSEQ * DINNER;
    const int t0 = c * CHUNK;

    const float w0 = conv_w[d * DCONV + 0];
    const float w1 = conv_w[d * DCONV + 1];
    const float w2 = conv_w[d * DCONV + 2];
    const float w3 = conv_w[d * DCONV + 3];
    const float bias = conv_b[d];
    const float Dp = D_param[d];

    float Aval[DSTATE];
    #pragma unroll
    for (int s = 0; s < DSTATE; s++)
        Aval[s] = -expf(A_log[s * DINNER + d]);

    float st[DSTATE];
    {
        const float* cs = g_cs + ((size_t)(b * NCH + c) * DSTATE) * DINNER + d;
        #pragma unroll
        for (int s = 0; s < DSTATE; s++) st[s] = cs[(size_t)s * DINNER];
    }

    float x0 = 0.f, x1 = 0.f, x2 = 0.f, x3 = 0.f;
    if (c > 0) {
        x1 = xz[(size_t)(t0 - 3) * (2 * DINNER) + d];
        x2 = xz[(size_t)(t0 - 2) * (2 * DINNER) + d];
        x3 = xz[(size_t)(t0 - 1) * (2 * DINNER) + d];
    }

    constexpr int U = 8;
    for (int tt = 0; tt < CHUNK; tt += U) {
        float uv[U], zv[U];
        #pragma unroll
        for (int i = 0; i < U; i++) {
            const size_t off = (size_t)(t0 + tt + i) * (2 * DINNER) + d;
            uv[i] = xz[off];
            zv[i] = xz[off + DINNER];
        }
        #pragma unroll
        for (int i = 0; i < U; i++) {
            x0 = x1; x1 = x2; x2 = x3; x3 = uv[i];
            float uc = fmaf(w0, x0, fmaf(w1, x1, fmaf(w2, x2, fmaf(w3, x3, bias))));
            float acc = Dp * uc;
            #pragma unroll
            for (int s = 0; s < DSTATE; s++) {
                st[s] = fmaf(st[s], Aval[s], uc);
                acc += st[s];
            }
            const float z = zv[i];
            const float sig = 1.0f / (1.0f + expf(-z));
            yh[(size_t)(t0 + tt + i) * DINNER + d] = __float2half(acc * (z * sig));
        }
    }
}

// ---------------------------------------------------------------------------
extern "C" void kernel_launch(void* const* d_in, const int* in_sizes, int n_in,
                              void* d_out, int out_size)
{
    const float* x       = (const float*)d_in[0];
    const float* W_in    = (const float*)d_in[1];
    const float* conv_w  = (const float*)d_in[2];
    const float* conv_b  = (const float*)d_in[3];
    const float* A_log   = (const float*)d_in[4];
    const float* D_param = (const float*)d_in[5];
    const float* W_out   = (const float*)d_in[6];
    float* out = (float*)d_out;

    float *xz_p;
    __half *xh_p, *winh_p, *winl_p, *wouth_p, *woutl_p, *yh_p;
    cudaGetSymbolAddress((void**)&xz_p,    g_xz);
    cudaGetSymbolAddress((void**)&xh_p,    g_xh);
    cudaGetSymbolAddress((void**)&winh_p,  g_WinT_hi);
    cudaGetSymbolAddress((void**)&winl_p,  g_WinT_lo);
    cudaGetSymbolAddress((void**)&wouth_p, g_WoutT_hi);
    cudaGetSymbolAddress((void**)&woutl_p, g_WoutT_lo);
    cudaGetSymbolAddress((void**)&yh_p,    g_yh);

    // opt-in smem: NPASS=2 -> 3*48KB, NPASS=1 -> 3*32KB (+ align pad)
    const int SMEM2 = 3 * 3 * 128 * 128 + 1024;
    const int SMEM1 = 3 * 2 * 128 * 128 + 1024;
    cudaFuncSetAttribute(gemm_f16<2>,
                         cudaFuncAttributeMaxDynamicSharedMemorySize, SMEM2);
    cudaFuncSetAttribute(gemm_f16<1>,
                         cudaFuncAttributeMaxDynamicSharedMemorySize, SMEM1);

    // 1) Round x to fp16
    {
        const int n4 = MTOK * DMODEL / 4;
        round_f16<<<(n4 + 255) / 256, 256>>>(x, xh_p, n4);
    }
    // 2) Transpose+split weights (fp16 hi/lo; W_out lo unused but cheap)
    {
        dim3 blk(32, 8);
        dim3 g1(2 * DINNER / 32, DMODEL / 32);
        transpose_split<<<g1, blk>>>(W_in, winh_p, winl_p, DMODEL, 2 * DINNER);
        dim3 g2(DMODEL / 32, DINNER / 32);
        transpose_split<<<g2, blk>>>(W_out, wouth_p, woutl_p, DINNER, DMODEL);
    }
    // 3) GEMM1 (2-pass): xz = x @ W_in
    {
        dim3 grid(2 * DINNER / 128, MTOK / 128);
        gemm_f16<2><<<grid, 512, SMEM2>>>(MTOK, 2 * DINNER, DMODEL,
                                          xh_p, winh_p, winl_p, xz_p);
    }
    // 4) Chunked conv+scan+gate (3 passes)
    scan_pass1 <<<(BSZ * NCH * DINNER) / 256, 256>>>(conv_w, conv_b, A_log);
    scan_combine<<<(BSZ * DINNER) / 256, 256>>>(A_log);
    scan_pass2 <<<(BSZ * NCH * DINNER) / 256, 256>>>(conv_w, conv_b, A_log, D_param);
    // 5) GEMM2 (1-pass): out = y @ W_out
    {
        dim3 grid(DMODEL / 128, MTOK / 128);
        gemm_f16<1><<<grid, 512, SMEM1>>>(MTOK, DMODEL, DINNER,
                                          yh_p, wouth_p, woutl_p, out);
    }
}

// round 14
// speedup vs baseline: 1.4825x; 1.2868x over previous
#include <cuda_runtime.h>
#include <cuda_fp16.h>
#include <math.h>
#include <stdint.h>

// Problem constants (fixed shapes)
#define BSZ     4
#define LSEQ    2048
#define DMODEL  1024
#define DSTATE  16
#define DCONV   4
#define DINNER  2048
#define MTOK    (BSZ * LSEQ)            // 8192 tokens
#define CHUNK   128
#define NCH     (LSEQ / CHUNK)          // 16 chunks

// ---------------------------------------------------------------------------
// Static device scratch (no cudaMalloc allowed)
// ---------------------------------------------------------------------------
__device__ float  g_xz[(size_t)MTOK * 2 * DINNER];          // (8192, 4096) fp32
__device__ __half g_xh[(size_t)MTOK * DMODEL];              // x rounded fp16
__device__ __half g_WinT_hi[(size_t)2 * DINNER * DMODEL];   // W_in^T hi (4096,1024)
__device__ __half g_WinT_lo[(size_t)2 * DINNER * DMODEL];   // (kept as rollback)
__device__ __half g_WoutT_hi[(size_t)DMODEL * DINNER];      // W_out^T hi (1024,2048)
__device__ __half g_WoutT_lo[(size_t)DMODEL * DINNER];      // (kept as rollback)
__device__ __half g_yh[(size_t)MTOK * DINNER];              // scan output fp16
__device__ float  g_cs[(size_t)BSZ * NCH * DSTATE * DINNER];// chunk states, 8 MB

// ---------------------------------------------------------------------------
// PTX helpers (sm_80+ only: ldmatrix / mma.sync / cp.async)
// ---------------------------------------------------------------------------
__device__ __forceinline__ uint32_t smem_u32(const void* p) {
    uint32_t a;
    asm("{ .reg .u64 t; cvta.to.shared.u64 t, %1; cvt.u32.u64 %0, t; }"
        : "=r"(a) : "l"(p));
    return a;
}

__device__ __forceinline__ void ldsm_x4(uint32_t* r, uint32_t addr) {
    asm volatile("ldmatrix.sync.aligned.m8n8.x4.shared.b16 {%0,%1,%2,%3}, [%4];"
                 : "=r"(r[0]), "=r"(r[1]), "=r"(r[2]), "=r"(r[3]) : "r"(addr));
}

__device__ __forceinline__ void mma_f16(float* c, const uint32_t* a,
                                        uint32_t b0, uint32_t b1) {
    asm volatile(
        "mma.sync.aligned.m16n8k16.row.col.f32.f16.f16.f32 "
        "{%0,%1,%2,%3}, {%4,%5,%6,%7}, {%8,%9}, {%0,%1,%2,%3};"
        : "+f"(c[0]), "+f"(c[1]), "+f"(c[2]), "+f"(c[3])
        : "r"(a[0]), "r"(a[1]), "r"(a[2]), "r"(a[3]), "r"(b0), "r"(b1));
}

__device__ __forceinline__ void cp_async16(uint32_t saddr, const void* gptr) {
    asm volatile("cp.async.cg.shared.global [%0], [%1], 16;"
                 :: "r"(saddr), "l"(gptr));
}
#define CP_COMMIT() asm volatile("cp.async.commit_group;" ::: "memory")
#define CP_WAIT(n)  asm volatile("cp.async.wait_group %0;" :: "n"(n) : "memory")

// ---------------------------------------------------------------------------
// fp16 split GEMM, NPASS template:  C[M,N] = A[M,K] @ B[N,K]^T  (fp32 out)
//   A: fp16-rounded [M,K].
//   NPASS=2: B split hi/lo, C = A*Bhi + A*Blo (both fp32 acc).
//   NPASS=1: B hi only (adds ~2.1e-4 quadrature error per converted path).
// CTA 128x128, BK=64, 512 threads (16 warps, 4x4, 32x32 warp tiles).
// 3-stage cp.async ring ((1+NPASS)*16KB per stage), ONE barrier per k-tile.
// SW128 swizzle: 16B chunk index ^= (row & 7).
// ---------------------------------------------------------------------------
template <int NPASS>
__global__ __launch_bounds__(512, 1) void gemm_f16(
    int M, int N, int K,
    const __half* __restrict__ Ah,
    const __half* __restrict__ Bhi,
    const __half* __restrict__ Blo,
    float* __restrict__ C)
{
    constexpr int TILE_B = 128 * 128;           // 16KB per operand tile
    constexpr int NOP = 1 + NPASS;              // operands per stage
    constexpr int STAGE_B = TILE_B * NOP;
    constexpr int BK = 64;
    constexpr int NSTAGE = 3;
    constexpr int CHUNKS = NOP * 1024;          // 16B chunks per stage
    constexpr int PER_THR = CHUNKS / 512;

    extern __shared__ char dsmem_raw[];
    const uint32_t raw_u32 = smem_u32(dsmem_raw);
    const uint32_t base = (raw_u32 + 1023u) & ~1023u;

    const int tid = threadIdx.x;
    const int wid = tid >> 5;
    const int lane = tid & 31;
    const int warpM = wid & 3;
    const int warpN = wid >> 2;
    const int blockRow = blockIdx.y;
    const int blockCol = blockIdx.x;

    const __half* opSrc[3] = { Ah, Bhi, Blo };

    auto loadStageAsync = [&](int stage, int k0) {
        #pragma unroll
        for (int i = 0; i < PER_THR; i++) {
            const int idx = tid + 512 * i;
            const int operand = idx >> 10;        // 0..NOP-1
            const int rem = idx & 1023;
            const int row = rem >> 3;             // 0..127
            const int chunk = rem & 7;            // 0..7
            const int gRow = (operand == 0 ? blockRow : blockCol) * 128 + row;
            const __half* src = opSrc[operand] + (size_t)gRow * K + k0 + chunk * 8;
            const uint32_t saddr = base + stage * STAGE_B + operand * TILE_B
                                 + row * 128 + ((chunk ^ (row & 7)) << 4);
            cp_async16(saddr, src);
        }
    };

    float acc[2][4][4];
    #pragma unroll
    for (int m = 0; m < 2; m++)
        #pragma unroll
        for (int n = 0; n < 4; n++)
            #pragma unroll
            for (int j = 0; j < 4; j++) acc[m][n][j] = 0.0f;

    const int nK = K / BK;
    loadStageAsync(0, 0);
    CP_COMMIT();
    if (nK > 1) { loadStageAsync(1, BK); CP_COMMIT(); }

    for (int t = 0; t < nK; t++) {
        if (t + 1 < nK) { CP_WAIT(1); } else { CP_WAIT(0); }
        __syncthreads();   // all threads done with compute(t-1) AND see stage t

        if (t + 2 < nK) { loadStageAsync((t + 2) % NSTAGE, (t + 2) * BK); CP_COMMIT(); }

        const uint32_t sbase = base + (t % NSTAGE) * STAGE_B;
        const uint32_t sA = sbase;

        #pragma unroll
        for (int ks = 0; ks < 4; ks++) {
            const int chunk = ks * 2 + (lane >> 4);

            uint32_t afr[2][4];
            #pragma unroll
            for (int mt = 0; mt < 2; mt++) {
                const int row = warpM * 32 + mt * 16 + (lane & 15);
                ldsm_x4(afr[mt], sA + row * 128 + ((chunk ^ (row & 7)) << 4));
            }

            uint32_t bfr[NPASS][2][4];
            #pragma unroll
            for (int p = 0; p < NPASS; p++)
                #pragma unroll
                for (int np = 0; np < 2; np++) {
                    const int row = warpN * 32 + np * 16 + (lane & 15);
                    const uint32_t off = row * 128 + ((chunk ^ (row & 7)) << 4);
                    ldsm_x4(bfr[p][np], sbase + (1 + p) * TILE_B + off);
                }

            #pragma unroll
            for (int p = 0; p < NPASS; p++)
                #pragma unroll
                for (int mt = 0; mt < 2; mt++)
                    #pragma unroll
                    for (int np = 0; np < 2; np++)
                        #pragma unroll
                        for (int h = 0; h < 2; h++)
                            mma_f16(acc[mt][np * 2 + h], afr[mt],
                                    bfr[p][np][h], bfr[p][np][h + 2]);
        }
        // next iteration's single barrier protects the ring slot (dist 2 of 3)
    }

    const int g = lane >> 2;
    const int tcol = (lane & 3) * 2;
    #pragma unroll
    for (int mt = 0; mt < 2; mt++) {
        const int r0 = blockRow * 128 + warpM * 32 + mt * 16 + g;
        #pragma unroll
        for (int n = 0; n < 4; n++) {
            const int col = blockCol * 128 + warpN * 32 + n * 8 + tcol;
            float2 v01 = make_float2(acc[mt][n][0], acc[mt][n][1]);
            float2 v23 = make_float2(acc[mt][n][2], acc[mt][n][3]);
            *reinterpret_cast<float2*>(C + (size_t)r0 * N + col) = v01;
            *reinterpret_cast<float2*>(C + (size_t)(r0 + 8) * N + col) = v23;
        }
    }
}

// ---------------------------------------------------------------------------
// Elementwise fp32 -> fp16 round (vectorized).
// ---------------------------------------------------------------------------
__global__ __launch_bounds__(256) void round_f16(
    const float* __restrict__ in, __half* __restrict__ outh, int n4)
{
    const int idx = blockIdx.x * blockDim.x + threadIdx.x;
    if (idx >= n4) return;
    const float4 v = reinterpret_cast<const float4*>(in)[idx];
    __half h[4] = { __float2half(v.x), __float2half(v.y),
                    __float2half(v.z), __float2half(v.w) };
    reinterpret_cast<uint2*>(outh)[idx] = *reinterpret_cast<uint2*>(h);
}

// ---------------------------------------------------------------------------
// Transposed split: W[K,N] fp32 -> Th/Tl[N,K] fp16 hi/lo.
// ---------------------------------------------------------------------------
__global__ __launch_bounds__(256) void transpose_split(
    const float* __restrict__ W,
    __half* __restrict__ Th,
    __half* __restrict__ Tl,
    int K, int N)
{
    __shared__ float tile[32][33];
    const int k0 = blockIdx.y * 32;
    const int n0 = blockIdx.x * 32;
    const int tx = threadIdx.x;
    const int ty = threadIdx.y;

    #pragma unroll
    for (int r = ty; r < 32; r += 8)
        tile[r][tx] = W[(size_t)(k0 + r) * N + n0 + tx];
    __syncthreads();

    #pragma unroll
    for (int r = ty; r < 32; r += 8) {
        const float v = tile[tx][r];
        const __half h = __float2half(v);
        const __half l = __float2half(v - __half2float(h));
        const size_t o = (size_t)(n0 + r) * K + k0 + tx;
        Th[o] = h;
        Tl[o] = l;
    }
}

// ---------------------------------------------------------------------------
// Chunked scan, pass 1: per (b, chunk, d) conv + 128-step scan from zero
// state; write the 16 final states to g_cs.
// ---------------------------------------------------------------------------
__global__ __launch_bounds__(256) void scan_pass1(
    const float* __restrict__ conv_w,
    const float* __restrict__ conv_b,
    const float* __restrict__ A_log)
{
    const int gid = blockIdx.x * blockDim.x + threadIdx.x;
    const int d = gid & (DINNER - 1);
    const int rest = gid >> 11;
    const int c = rest & (NCH - 1);
    const int b = rest >> 4;

    const float* xz = g_xz + (size_t)b * LSEQ * (2 * DINNER);
    const int t0 = c * CHUNK;

    const float w0 = conv_w[d * DCONV + 0];
    const float w1 = conv_w[d * DCONV + 1];
    const float w2 = conv_w[d * DCONV + 2];
    const float w3 = conv_w[d * DCONV + 3];
    const float bias = conv_b[d];

    float Aval[DSTATE];
    #pragma unroll
    for (int s = 0; s < DSTATE; s++)
        Aval[s] = -expf(A_log[s * DINNER + d]);

    float st[DSTATE];
    #pragma unroll
    for (int s = 0; s < DSTATE; s++) st[s] = 0.0f;

    float x0 = 0.f, x1 = 0.f, x2 = 0.f, x3 = 0.f;
    if (c > 0) {
        x1 = xz[(size_t)(t0 - 3) * (2 * DINNER) + d];
        x2 = xz[(size_t)(t0 - 2) * (2 * DINNER) + d];
        x3 = xz[(size_t)(t0 - 1) * (2 * DINNER) + d];
    }

    constexpr int U = 8;
    for (int tt = 0; tt < CHUNK; tt += U) {
        float uv[U];
        #pragma unroll
        for (int i = 0; i < U; i++)
            uv[i] = xz[(size_t)(t0 + tt + i) * (2 * DINNER) + d];
        #pragma unroll
        for (int i = 0; i < U; i++) {
            x0 = x1; x1 = x2; x2 = x3; x3 = uv[i];
            float uc = fmaf(w0, x0, fmaf(w1, x1, fmaf(w2, x2, fmaf(w3, x3, bias))));
            #pragma unroll
            for (int s = 0; s < DSTATE; s++)
                st[s] = fmaf(st[s], Aval[s], uc);
        }
    }

    float* cs = g_cs + ((size_t)(b * NCH + c) * DSTATE) * DINNER + d;
    #pragma unroll
    for (int s = 0; s < DSTATE; s++)
        cs[(size_t)s * DINNER] = st[s];
}

// ---------------------------------------------------------------------------
// Chunked scan, pass 2 (combine): init[0]=0; init[c]=A^128*init[c-1]+lf[c-1]
// ---------------------------------------------------------------------------
__global__ __launch_bounds__(256) void scan_combine(
    const float* __restrict__ A_log)
{
    const int gid = blockIdx.x * blockDim.x + threadIdx.x;
    const int d = gid & (DINNER - 1);
    const int b = gid >> 11;

    float A128[DSTATE];
    #pragma unroll
    for (int s = 0; s < DSTATE; s++)
        A128[s] = expf(128.0f * A_log[s * DINNER + d]);

    float init[DSTATE];
    #pragma unroll
    for (int s = 0; s < DSTATE; s++) init[s] = 0.0f;

    for (int c = 0; c < NCH; c++) {
        float* cs = g_cs + ((size_t)(b * NCH + c) * DSTATE) * DINNER + d;
        float lf[DSTATE];
        #pragma unroll
        for (int s = 0; s < DSTATE; s++) lf[s] = cs[(size_t)s * DINNER];
        #pragma unroll
        for (int s = 0; s < DSTATE; s++) cs[(size_t)s * DINNER] = init[s];
        #pragma unroll
        for (int s = 0; s < DSTATE; s++)
            init[s] = fmaf(A128[s], init[s], lf[s]);
    }
}

// ---------------------------------------------------------------------------
// Chunked scan, pass 3: rescan from correct initial state, D skip + silu
// gate, emit y as single fp16.
// ---------------------------------------------------------------------------
__global__ __launch_bounds__(256) void scan_pass2(
    const float* __restrict__ conv_w,
    const float* __restrict__ conv_b,
    const float* __restrict__ A_log,
    const float* __restrict__ D_param)
{
    const int gid = blockIdx.x * blockDim.x + threadIdx.x;
    const int d = gid & (DINNER - 1);
    const int rest = gid >> 11;
    const int c = rest & (NCH - 1);
    const int b = rest >> 4;

    const float* xz = g_xz + (size_t)b * LSEQ * (2 * DINNER);
    __half* yh = g_yh + (size_t)b * LSEQ * DINNER;
    const int t0 = c * CHUNK;

    const float w0 = conv_w[d * DCONV + 0];
    const float w1 = conv_w[d * DCONV + 1];
    const float w2 = conv_w[d * DCONV + 2];
    const float w3 = conv_w[d * DCONV + 3];
    const float bias = conv_b[d];
    const float Dp = D_param[d];

    float Aval[DSTATE];
    #pragma unroll
    for (int s = 0; s < DSTATE; s++)
        Aval[s] = -expf(A_log[s * DINNER + d]);

    float st[DSTATE];
    {
        const float* cs = g_cs + ((size_t)(b * NCH + c) * DSTATE) * DINNER + d;
        #pragma unroll
        for (int s = 0; s < DSTATE; s++) st[s] = cs[(size_t)s * DINNER];
    }

    float x0 = 0.f, x1 = 0.f, x2 = 0.f, x3 = 0.f;
    if (c > 0) {
        x1 = xz[(size_t)(t0 - 3) * (2 * DINNER) + d];
        x2 = xz[(size_t)(t0 - 2) * (2 * DINNER) + d];
        x3 = xz[(size_t)(t0 - 1) * (2 * DINNER) + d];
    }

    constexpr int U = 8;
    for (int tt = 0; tt < CHUNK; tt += U) {
        float uv[U], zv[U];
        #pragma unroll
        for (int i = 0; i < U; i++) {
            const size_t off = (size_t)(t0 + tt + i) * (2 * DINNER) + d;
            uv[i] = xz[off];
            zv[i] = xz[off + DINNER];
        }
        #pragma unroll
        for (int i = 0; i < U; i++) {
            x0 = x1; x1 = x2; x2 = x3; x3 = uv[i];
            float uc = fmaf(w0, x0, fmaf(w1, x1, fmaf(w2, x2, fmaf(w3, x3, bias))));
            float acc = Dp * uc;
            #pragma unroll
            for (int s = 0; s < DSTATE; s++) {
                st[s] = fmaf(st[s], Aval[s], uc);
                acc += st[s];
            }
            const float z = zv[i];
            const float sig = 1.0f / (1.0f + expf(-z));
            yh[(size_t)(t0 + tt + i) * DINNER + d] = __float2half(acc * (z * sig));
        }
    }
}

// ---------------------------------------------------------------------------
extern "C" void kernel_launch(void* const* d_in, const int* in_sizes, int n_in,
                              void* d_out, int out_size)
{
    const float* x       = (const float*)d_in[0];
    const float* W_in    = (const float*)d_in[1];
    const float* conv_w  = (const float*)d_in[2];
    const float* conv_b  = (const float*)d_in[3];
    const float* A_log   = (const float*)d_in[4];
    const float* D_param = (const float*)d_in[5];
    const float* W_out   = (const float*)d_in[6];
    float* out = (float*)d_out;

    float *xz_p;
    __half *xh_p, *winh_p, *winl_p, *wouth_p, *woutl_p, *yh_p;
    cudaGetSymbolAddress((void**)&xz_p,    g_xz);
    cudaGetSymbolAddress((void**)&xh_p,    g_xh);
    cudaGetSymbolAddress((void**)&winh_p,  g_WinT_hi);
    cudaGetSymbolAddress((void**)&winl_p,  g_WinT_lo);
    cudaGetSymbolAddress((void**)&wouth_p, g_WoutT_hi);
    cudaGetSymbolAddress((void**)&woutl_p, g_WoutT_lo);
    cudaGetSymbolAddress((void**)&yh_p,    g_yh);

    // opt-in smem: NPASS=1 -> 3*32KB (+ align pad); NPASS=2 kept as rollback
    const int SMEM2 = 3 * 3 * 128 * 128 + 1024;
    const int SMEM1 = 3 * 2 * 128 * 128 + 1024;
    cudaFuncSetAttribute(gemm_f16<2>,
                         cudaFuncAttributeMaxDynamicSharedMemorySize, SMEM2);
    cudaFuncSetAttribute(gemm_f16<1>,
                         cudaFuncAttributeMaxDynamicSharedMemorySize, SMEM1);

    // 1) Round x to fp16
    {
        const int n4 = MTOK * DMODEL / 4;
        round_f16<<<(n4 + 255) / 256, 256>>>(x, xh_p, n4);
    }
    // 2) Transpose+split weights (lo halves kept as the rollback path)
    {
        dim3 blk(32, 8);
        dim3 g1(2 * DINNER / 32, DMODEL / 32);
        transpose_split<<<g1, blk>>>(W_in, winh_p, winl_p, DMODEL, 2 * DINNER);
        dim3 g2(DMODEL / 32, DINNER / 32);
        transpose_split<<<g2, blk>>>(W_out, wouth_p, woutl_p, DINNER, DMODEL);
    }
    // 3) GEMM1 (1-pass): xz = x @ W_in
    {
        dim3 grid(2 * DINNER / 128, MTOK / 128);
        gemm_f16<1><<<grid, 512, SMEM1>>>(MTOK, 2 * DINNER, DMODEL,
                                          xh_p, winh_p, winl_p, xz_p);
    }
    // 4) Chunked conv+scan+gate (3 passes)
    scan_pass1 <<<(BSZ * NCH * DINNER) / 256, 256>>>(conv_w, conv_b, A_log);
    scan_combine<<<(BSZ * DINNER) / 256, 256>>>(A_log);
    scan_pass2 <<<(BSZ * NCH * DINNER) / 256, 256>>>(conv_w, conv_b, A_log, D_param);
    // 5) GEMM2 (1-pass): out = y @ W_out
    {
        dim3 grid(DMODEL / 128, MTOK / 128);
        gemm_f16<1><<<grid, 512, SMEM1>>>(MTOK, DMODEL, DINNER,
                                          yh_p, wouth_p, woutl_p, out);
    }
}

// round 15
// speedup vs baseline: 1.5537x; 1.0480x over previous
#include <cuda_runtime.h>
#include <cuda_fp16.h>
#include <math.h>
#include <stdint.h>

// Problem constants (fixed shapes)
#define BSZ     4
#define LSEQ    2048
#define DMODEL  1024
#define DSTATE  16
#define DCONV   4
#define DINNER  2048
#define MTOK    (BSZ * LSEQ)            // 8192 tokens
#define CHUNK   128
#define NCH     (LSEQ / CHUNK)          // 16 chunks

// ---------------------------------------------------------------------------
// Static device scratch (no cudaMalloc allowed)
// ---------------------------------------------------------------------------
__device__ float  g_xz[(size_t)MTOK * 2 * DINNER];          // (8192, 4096) fp32
__device__ __half g_xh[(size_t)MTOK * DMODEL];              // x rounded fp16
__device__ __half g_WinT_hi[(size_t)2 * DINNER * DMODEL];   // W_in^T hi (4096,1024)
__device__ __half g_WinT_lo[(size_t)2 * DINNER * DMODEL];   // (kept as rollback)
__device__ __half g_WoutT_hi[(size_t)DMODEL * DINNER];      // W_out^T hi (1024,2048)
__device__ __half g_WoutT_lo[(size_t)DMODEL * DINNER];      // (kept as rollback)
__device__ __half g_yh[(size_t)MTOK * DINNER];              // scan output fp16
__device__ float  g_cs[(size_t)BSZ * NCH * DSTATE * DINNER];// chunk states, 8 MB

// ---------------------------------------------------------------------------
// PTX helpers (sm_80+ only: ldmatrix / mma.sync / cp.async)
// ---------------------------------------------------------------------------
__device__ __forceinline__ uint32_t smem_u32(const void* p) {
    uint32_t a;
    asm("{ .reg .u64 t; cvta.to.shared.u64 t, %1; cvt.u32.u64 %0, t; }"
        : "=r"(a) : "l"(p));
    return a;
}

__device__ __forceinline__ void ldsm_x4(uint32_t* r, uint32_t addr) {
    asm volatile("ldmatrix.sync.aligned.m8n8.x4.shared.b16 {%0,%1,%2,%3}, [%4];"
                 : "=r"(r[0]), "=r"(r[1]), "=r"(r[2]), "=r"(r[3]) : "r"(addr));
}

__device__ __forceinline__ void mma_f16(float* c, const uint32_t* a,
                                        uint32_t b0, uint32_t b1) {
    asm volatile(
        "mma.sync.aligned.m16n8k16.row.col.f32.f16.f16.f32 "
        "{%0,%1,%2,%3}, {%4,%5,%6,%7}, {%8,%9}, {%0,%1,%2,%3};"
        : "+f"(c[0]), "+f"(c[1]), "+f"(c[2]), "+f"(c[3])
        : "r"(a[0]), "r"(a[1]), "r"(a[2]), "r"(a[3]), "r"(b0), "r"(b1));
}

__device__ __forceinline__ void cp_async16(uint32_t saddr, const void* gptr) {
    asm volatile("cp.async.cg.shared.global [%0], [%1], 16;"
                 :: "r"(saddr), "l"(gptr));
}
#define CP_COMMIT() asm volatile("cp.async.commit_group;" ::: "memory")
#define CP_WAIT(n)  asm volatile("cp.async.wait_group %0;" :: "n"(n) : "memory")

// ---------------------------------------------------------------------------
// fp16 split GEMM, NPASS template:  C[M,N] = A[M,K] @ B[N,K]^T  (fp32 out)
//   A: fp16-rounded [M,K].
//   NPASS=2: B split hi/lo, C = A*Bhi + A*Blo (both fp32 acc).
//   NPASS=1: B hi only.
// CTA 128x128, BK=64, 256 threads (8 warps, 4x2 grid, 32x64 warp tiles) —
// 16 mma : 6 ldsm per warp per k-chunk (NPASS=1) keeps the tensor queue fed.
// 3-stage cp.async ring ((1+NPASS)*16KB per stage), ONE barrier per k-tile.
// SW128 swizzle: 16B chunk index ^= (row & 7).
// ---------------------------------------------------------------------------
template <int NPASS>
__global__ __launch_bounds__(256, 1) void gemm_f16(
    int M, int N, int K,
    const __half* __restrict__ Ah,
    const __half* __restrict__ Bhi,
    const __half* __restrict__ Blo,
    float* __restrict__ C)
{
    constexpr int TILE_B = 128 * 128;           // 16KB per operand tile
    constexpr int NOP = 1 + NPASS;              // operands per stage
    constexpr int STAGE_B = TILE_B * NOP;
    constexpr int BK = 64;
    constexpr int NSTAGE = 3;
    constexpr int CHUNKS = NOP * 1024;          // 16B chunks per stage
    constexpr int PER_THR = CHUNKS / 256;

    extern __shared__ char dsmem_raw[];
    const uint32_t raw_u32 = smem_u32(dsmem_raw);
    const uint32_t base = (raw_u32 + 1023u) & ~1023u;

    const int tid = threadIdx.x;
    const int wid = tid >> 5;
    const int lane = tid & 31;
    const int warpM = wid & 3;                  // 0..3 -> 32-row slice
    const int warpN = wid >> 2;                 // 0..1 -> 64-col slice
    const int blockRow = blockIdx.y;
    const int blockCol = blockIdx.x;

    const __half* opSrc[3] = { Ah, Bhi, Blo };

    auto loadStageAsync = [&](int stage, int k0) {
        #pragma unroll
        for (int i = 0; i < PER_THR; i++) {
            const int idx = tid + 256 * i;
            const int operand = idx >> 10;        // 0..NOP-1
            const int rem = idx & 1023;
            const int row = rem >> 3;             // 0..127
            const int chunk = rem & 7;            // 0..7
            const int gRow = (operand == 0 ? blockRow : blockCol) * 128 + row;
            const __half* src = opSrc[operand] + (size_t)gRow * K + k0 + chunk * 8;
            const uint32_t saddr = base + stage * STAGE_B + operand * TILE_B
                                 + row * 128 + ((chunk ^ (row & 7)) << 4);
            cp_async16(saddr, src);
        }
    };

    float acc[2][8][4];                         // [mtile][n8tile][frag]
    #pragma unroll
    for (int m = 0; m < 2; m++)
        #pragma unroll
        for (int n = 0; n < 8; n++)
            #pragma unroll
            for (int j = 0; j < 4; j++) acc[m][n][j] = 0.0f;

    const int nK = K / BK;
    loadStageAsync(0, 0);
    CP_COMMIT();
    if (nK > 1) { loadStageAsync(1, BK); CP_COMMIT(); }

    for (int t = 0; t < nK; t++) {
        if (t + 1 < nK) { CP_WAIT(1); } else { CP_WAIT(0); }
        __syncthreads();   // all threads done with compute(t-1) AND see stage t

        if (t + 2 < nK) { loadStageAsync((t + 2) % NSTAGE, (t + 2) * BK); CP_COMMIT(); }

        const uint32_t sbase = base + (t % NSTAGE) * STAGE_B;
        const uint32_t sA = sbase;

        #pragma unroll
        for (int ks = 0; ks < 4; ks++) {
            const int chunk = ks * 2 + (lane >> 4);

            uint32_t afr[2][4];                 // [mtile][regs]
            #pragma unroll
            for (int mt = 0; mt < 2; mt++) {
                const int row = warpM * 32 + mt * 16 + (lane & 15);
                ldsm_x4(afr[mt], sA + row * 128 + ((chunk ^ (row & 7)) << 4));
            }

            uint32_t bfr[NPASS][4][4];          // [pass][npair(16 rows)][regs]
            #pragma unroll
            for (int p = 0; p < NPASS; p++)
                #pragma unroll
                for (int np = 0; np < 4; np++) {
                    const int row = warpN * 64 + np * 16 + (lane & 15);
                    const uint32_t off = row * 128 + ((chunk ^ (row & 7)) << 4);
                    ldsm_x4(bfr[p][np], sbase + (1 + p) * TILE_B + off);
                }

            #pragma unroll
            for (int p = 0; p < NPASS; p++)
                #pragma unroll
                for (int mt = 0; mt < 2; mt++)
                    #pragma unroll
                    for (int np = 0; np < 4; np++)
                        #pragma unroll
                        for (int h = 0; h < 2; h++)
                            mma_f16(acc[mt][np * 2 + h], afr[mt],
                                    bfr[p][np][h], bfr[p][np][h + 2]);
        }
        // next iteration's single barrier protects the ring slot (dist 2 of 3)
    }

    const int g = lane >> 2;
    const int tcol = (lane & 3) * 2;
    #pragma unroll
    for (int mt = 0; mt < 2; mt++) {
        const int r0 = blockRow * 128 + warpM * 32 + mt * 16 + g;
        #pragma unroll
        for (int n = 0; n < 8; n++) {
            const int col = blockCol * 128 + warpN * 64 + n * 8 + tcol;
            float2 v01 = make_float2(acc[mt][n][0], acc[mt][n][1]);
            float2 v23 = make_float2(acc[mt][n][2], acc[mt][n][3]);
            *reinterpret_cast<float2*>(C + (size_t)r0 * N + col) = v01;
            *reinterpret_cast<float2*>(C + (size_t)(r0 + 8) * N + col) = v23;
        }
    }
}

// ---------------------------------------------------------------------------
// Elementwise fp32 -> fp16 round (vectorized).
// ---------------------------------------------------------------------------
__global__ __launch_bounds__(256) void round_f16(
    const float* __restrict__ in, __half* __restrict__ outh, int n4)
{
    const int idx = blockIdx.x * blockDim.x + threadIdx.x;
    if (idx >= n4) return;
    const float4 v = reinterpret_cast<const float4*>(in)[idx];
    __half h[4] = { __float2half(v.x), __float2half(v.y),
                    __float2half(v.z), __float2half(v.w) };
    reinterpret_cast<uint2*>(outh)[idx] = *reinterpret_cast<uint2*>(h);
}

// ---------------------------------------------------------------------------
// Transposed split: W[K,N] fp32 -> Th/Tl[N,K] fp16 hi/lo.
// ---------------------------------------------------------------------------
__global__ __launch_bounds__(256) void transpose_split(
    const float* __restrict__ W,
    __half* __restrict__ Th,
    __half* __restrict__ Tl,
    int K, int N)
{
    __shared__ float tile[32][33];
    const int k0 = blockIdx.y * 32;
    const int n0 = blockIdx.x * 32;
    const int tx = threadIdx.x;
    const int ty = threadIdx.y;

    #pragma unroll
    for (int r = ty; r < 32; r += 8)
        tile[r][tx] = W[(size_t)(k0 + r) * N + n0 + tx];
    __syncthreads();

    #pragma unroll
    for (int r = ty; r < 32; r += 8) {
        const float v = tile[tx][r];
        const __half h = __float2half(v);
        const __half l = __float2half(v - __half2float(h));
        const size_t o = (size_t)(n0 + r) * K + k0 + tx;
        Th[o] = h;
        Tl[o] = l;
    }
}

// ---------------------------------------------------------------------------
// Chunked scan, pass 1: per (b, chunk, d) conv + 128-step scan from zero
// state; write the 16 final states to g_cs.
// ---------------------------------------------------------------------------
__global__ __launch_bounds__(256) void scan_pass1(
    const float* __restrict__ conv_w,
    const float* __restrict__ conv_b,
    const float* __restrict__ A_log)
{
    const int gid = blockIdx.x * blockDim.x + threadIdx.x;
    const int d = gid & (DINNER - 1);
    const int rest = gid >> 11;
    const int c = rest & (NCH - 1);
    const int b = rest >> 4;

    const float* xz = g_xz + (size_t)b * LSEQ * (2 * DINNER);
    const int t0 = c * CHUNK;

    const float w0 = conv_w[d * DCONV + 0];
    const float w1 = conv_w[d * DCONV + 1];
    const float w2 = conv_w[d * DCONV + 2];
    const float w3 = conv_w[d * DCONV + 3];
    const float bias = conv_b[d];

    float Aval[DSTATE];
    #pragma unroll
    for (int s = 0; s < DSTATE; s++)
        Aval[s] = -expf(A_log[s * DINNER + d]);

    float st[DSTATE];
    #pragma unroll
    for (int s = 0; s < DSTATE; s++) st[s] = 0.0f;

    float x0 = 0.f, x1 = 0.f, x2 = 0.f, x3 = 0.f;
    if (c > 0) {
        x1 = xz[(size_t)(t0 - 3) * (2 * DINNER) + d];
        x2 = xz[(size_t)(t0 - 2) * (2 * DINNER) + d];
        x3 = xz[(size_t)(t0 - 1) * (2 * DINNER) + d];
    }

    constexpr int U = 8;
    for (int tt = 0; tt < CHUNK; tt += U) {
        float uv[U];
        #pragma unroll
        for (int i = 0; i < U; i++)
            uv[i] = xz[(size_t)(t0 + tt + i) * (2 * DINNER) + d];
        #pragma unroll
        for (int i = 0; i < U; i++) {
            x0 = x1; x1 = x2; x2 = x3; x3 = uv[i];
            float uc = fmaf(w0, x0, fmaf(w1, x1, fmaf(w2, x2, fmaf(w3, x3, bias))));
            #pragma unroll
            for (int s = 0; s < DSTATE; s++)
                st[s] = fmaf(st[s], Aval[s], uc);
        }
    }

    float* cs = g_cs + ((size_t)(b * NCH + c) * DSTATE) * DINNER + d;
    #pragma unroll
    for (int s = 0; s < DSTATE; s++)
        cs[(size_t)s * DINNER] = st[s];
}

// ---------------------------------------------------------------------------
// Chunked scan, pass 2 (combine): init[0]=0; init[c]=A^128*init[c-1]+lf[c-1]
// ---------------------------------------------------------------------------
__global__ __launch_bounds__(256) void scan_combine(
    const float* __restrict__ A_log)
{
    const int gid = blockIdx.x * blockDim.x + threadIdx.x;
    const int d = gid & (DINNER - 1);
    const int b = gid >> 11;

    float A128[DSTATE];
    #pragma unroll
    for (int s = 0; s < DSTATE; s++)
        A128[s] = expf(128.0f * A_log[s * DINNER + d]);

    float init[DSTATE];
    #pragma unroll
    for (int s = 0; s < DSTATE; s++) init[s] = 0.0f;

    for (int c = 0; c < NCH; c++) {
        float* cs = g_cs + ((size_t)(b * NCH + c) * DSTATE) * DINNER + d;
        float lf[DSTATE];
        #pragma unroll
        for (int s = 0; s < DSTATE; s++) lf[s] = cs[(size_t)s * DINNER];
        #pragma unroll
        for (int s = 0; s < DSTATE; s++) cs[(size_t)s * DINNER] = init[s];
        #pragma unroll
        for (int s = 0; s < DSTATE; s++)
            init[s] = fmaf(A128[s], init[s], lf[s]);
    }
}

// ---------------------------------------------------------------------------
// Chunked scan, pass 3: rescan from correct initial state, D skip + silu
// gate, emit y as single fp16.
// ---------------------------------------------------------------------------
__global__ __launch_bounds__(256) void scan_pass2(
    const float* __restrict__ conv_w,
    const float* __restrict__ conv_b,
    const float* __restrict__ A_log,
    const float* __restrict__ D_param)
{
    const int gid = blockIdx.x * blockDim.x + threadIdx.x;
    const int d = gid & (DINNER - 1);
    const int rest = gid >> 11;
    const int c = rest & (NCH - 1);
    const int b = rest >> 4;

    const float* xz = g_xz + (size_t)b * LSEQ * (2 * DINNER);
    __half* yh = g_yh + (size_t)b * LSEQ * DINNER;
    const int t0 = c * CHUNK;

    const float w0 = conv_w[d * DCONV + 0];
    const float w1 = conv_w[d * DCONV + 1];
    const float w2 = conv_w[d * DCONV + 2];
    const float w3 = conv_w[d * DCONV + 3];
    const float bias = conv_b[d];
    const float Dp = D_param[d];

    float Aval[DSTATE];
    #pragma unroll
    for (int s = 0; s < DSTATE; s++)
        Aval[s] = -expf(A_log[s * DINNER + d]);

    float st[DSTATE];
    {
        const float* cs = g_cs + ((size_t)(b * NCH + c) * DSTATE) * DINNER + d;
        #pragma unroll
        for (int s = 0; s < DSTATE; s++) st[s] = cs[(size_t)s * DINNER];
    }

    float x0 = 0.f, x1 = 0.f, x2 = 0.f, x3 = 0.f;
    if (c > 0) {
        x1 = xz[(size_t)(t0 - 3) * (2 * DINNER) + d];
        x2 = xz[(size_t)(t0 - 2) * (2 * DINNER) + d];
        x3 = xz[(size_t)(t0 - 1) * (2 * DINNER) + d];
    }

    constexpr int U = 8;
    for (int tt = 0; tt < CHUNK; tt += U) {
        float uv[U], zv[U];
        #pragma unroll
        for (int i = 0; i < U; i++) {
            const size_t off = (size_t)(t0 + tt + i) * (2 * DINNER) + d;
            uv[i] = xz[off];
            zv[i] = xz[off + DINNER];
        }
        #pragma unroll
        for (int i = 0; i < U; i++) {
            x0 = x1; x1 = x2; x2 = x3; x3 = uv[i];
            float uc = fmaf(w0, x0, fmaf(w1, x1, fmaf(w2, x2, fmaf(w3, x3, bias))));
            float acc = Dp * uc;
            #pragma unroll
            for (int s = 0; s < DSTATE; s++) {
                st[s] = fmaf(st[s], Aval[s], uc);
                acc += st[s];
            }
            const float z = zv[i];
            const float sig = 1.0f / (1.0f + expf(-z));
            yh[(size_t)(t0 + tt + i) * DINNER + d] = __float2half(acc * (z * sig));
        }
    }
}

// ---------------------------------------------------------------------------
extern "C" void kernel_launch(void* const* d_in, const int* in_sizes, int n_in,
                              void* d_out, int out_size)
{
    const float* x       = (const float*)d_in[0];
    const float* W_in    = (const float*)d_in[1];
    const float* conv_w  = (const float*)d_in[2];
    const float* conv_b  = (const float*)d_in[3];
    const float* A_log   = (const float*)d_in[4];
    const float* D_param = (const float*)d_in[5];
    const float* W_out   = (const float*)d_in[6];
    float* out = (float*)d_out;

    float *xz_p;
    __half *xh_p, *winh_p, *winl_p, *wouth_p, *woutl_p, *yh_p;
    cudaGetSymbolAddress((void**)&xz_p,    g_xz);
    cudaGetSymbolAddress((void**)&xh_p,    g_xh);
    cudaGetSymbolAddress((void**)&winh_p,  g_WinT_hi);
    cudaGetSymbolAddress((void**)&winl_p,  g_WinT_lo);
    cudaGetSymbolAddress((void**)&wouth_p, g_WoutT_hi);
    cudaGetSymbolAddress((void**)&woutl_p, g_WoutT_lo);
    cudaGetSymbolAddress((void**)&yh_p,    g_yh);

    // opt-in smem: NPASS=1 -> 3*32KB (+ align pad); NPASS=2 kept as rollback
    const int SMEM2 = 3 * 3 * 128 * 128 + 1024;
    const int SMEM1 = 3 * 2 * 128 * 128 + 1024;
    cudaFuncSetAttribute(gemm_f16<2>,
                         cudaFuncAttributeMaxDynamicSharedMemorySize, SMEM2);
    cudaFuncSetAttribute(gemm_f16<1>,
                         cudaFuncAttributeMaxDynamicSharedMemorySize, SMEM1);

    // 1) Round x to fp16
    {
        const int n4 = MTOK * DMODEL / 4;
        round_f16<<<(n4 + 255) / 256, 256>>>(x, xh_p, n4);
    }
    // 2) Transpose+split weights (lo halves kept as the rollback path)
    {
        dim3 blk(32, 8);
        dim3 g1(2 * DINNER / 32, DMODEL / 32);
        transpose_split<<<g1, blk>>>(W_in, winh_p, winl_p, DMODEL, 2 * DINNER);
        dim3 g2(DMODEL / 32, DINNER / 32);
        transpose_split<<<g2, blk>>>(W_out, wouth_p, woutl_p, DINNER, DMODEL);
    }
    // 3) GEMM1 (1-pass): xz = x @ W_in
    {
        dim3 grid(2 * DINNER / 128, MTOK / 128);
        gemm_f16<1><<<grid, 256, SMEM1>>>(MTOK, 2 * DINNER, DMODEL,
                                          xh_p, winh_p, winl_p, xz_p);
    }
    // 4) Chunked conv+scan+gate (3 passes)
    scan_pass1 <<<(BSZ * NCH * DINNER) / 256, 256>>>(conv_w, conv_b, A_log);
    scan_combine<<<(BSZ * DINNER) / 256, 256>>>(A_log);
    scan_pass2 <<<(BSZ * NCH * DINNER) / 256, 256>>>(conv_w, conv_b, A_log, D_param);
    // 5) GEMM2 (1-pass): out = y @ W_out
    {
        dim3 grid(DMODEL / 128, MTOK / 128);
        gemm_f16<1><<<grid, 256, SMEM1>>>(MTOK, DMODEL, DINNER,
                                          yh_p, wouth_p, woutl_p, out);
    }
}

// round 16
// speedup vs baseline: 1.6133x; 1.0383x over previous
#include <cuda_runtime.h>
#include <cuda_fp16.h>
#include <math.h>
#include <stdint.h>

// Problem constants (fixed shapes)
#define BSZ     4
#define LSEQ    2048
#define DMODEL  1024
#define DSTATE  16
#define DCONV   4
#define DINNER  2048
#define MTOK    (BSZ * LSEQ)            // 8192 tokens
#define CHUNK   128
#define NCH     (LSEQ / CHUNK)          // 16 chunks

// ---------------------------------------------------------------------------
// Static device scratch (no cudaMalloc allowed)
// ---------------------------------------------------------------------------
__device__ float  g_xz[(size_t)MTOK * 2 * DINNER];          // (8192, 4096) fp32
__device__ __half g_xh[(size_t)MTOK * DMODEL];              // x rounded fp16
__device__ __half g_WinT_hi[(size_t)2 * DINNER * DMODEL];   // W_in^T hi (4096,1024)
__device__ __half g_WoutT_hi[(size_t)DMODEL * DINNER];      // W_out^T hi (1024,2048)
__device__ __half g_yh[(size_t)MTOK * DINNER];              // scan output fp16
__device__ float  g_cs[(size_t)BSZ * NCH * DSTATE * DINNER];// chunk states, 8 MB

// ---------------------------------------------------------------------------
// PTX helpers (sm_80+ only: ldmatrix / mma.sync / cp.async)
// ---------------------------------------------------------------------------
__device__ __forceinline__ uint32_t smem_u32(const void* p) {
    uint32_t a;
    asm("{ .reg .u64 t; cvta.to.shared.u64 t, %1; cvt.u32.u64 %0, t; }"
        : "=r"(a) : "l"(p));
    return a;
}

__device__ __forceinline__ void ldsm_x4(uint32_t* r, uint32_t addr) {
    asm volatile("ldmatrix.sync.aligned.m8n8.x4.shared.b16 {%0,%1,%2,%3}, [%4];"
                 : "=r"(r[0]), "=r"(r[1]), "=r"(r[2]), "=r"(r[3]) : "r"(addr));
}

__device__ __forceinline__ void mma_f16(float* c, const uint32_t* a,
                                        uint32_t b0, uint32_t b1) {
    asm volatile(
        "mma.sync.aligned.m16n8k16.row.col.f32.f16.f16.f32 "
        "{%0,%1,%2,%3}, {%4,%5,%6,%7}, {%8,%9}, {%0,%1,%2,%3};"
        : "+f"(c[0]), "+f"(c[1]), "+f"(c[2]), "+f"(c[3])
        : "r"(a[0]), "r"(a[1]), "r"(a[2]), "r"(a[3]), "r"(b0), "r"(b1));
}

__device__ __forceinline__ void cp_async16(uint32_t saddr, const void* gptr) {
    asm volatile("cp.async.cg.shared.global [%0], [%1], 16;"
                 :: "r"(saddr), "l"(gptr));
}
#define CP_COMMIT() asm volatile("cp.async.commit_group;" ::: "memory")
#define CP_WAIT(n)  asm volatile("cp.async.wait_group %0;" :: "n"(n) : "memory")

// ---------------------------------------------------------------------------
// fp16 1-pass GEMM:  C[M,N] = A[M,K] @ B[N,K]^T  (fp32 accum/out)
//   A: fp16-rounded [M,K];  B: fp16 hi [N,K].
// CTA 128x128, BK=128 (8 barriers for K=1024 vs 16 at BK=64 — halves the
// per-k-tile fixed overhead that throttled tensor% at NPASS=1).
// 256 threads (8 warps, 4x2 grid, 32x64 warp tiles).
// 3-stage cp.async ring (64KB/stage = A 32KB + B 32KB), ONE barrier/k-tile.
// 256B-row swizzle: csw = (chunk & 8) | ((chunk ^ row) & 7)  (16B chunks).
// ---------------------------------------------------------------------------
__global__ __launch_bounds__(256, 1) void gemm_f16_1p(
    int M, int N, int K,
    const __half* __restrict__ Ah,
    const __half* __restrict__ Bhi,
    float* __restrict__ C)
{
    constexpr int TILE_B = 128 * 256;           // 32KB per operand tile (BK=128)
    constexpr int STAGE_B = TILE_B * 2;         // A + B = 64KB
    constexpr int BK = 128;
    constexpr int NSTAGE = 3;
    constexpr int PER_THR = (2 * 2048) / 256;   // 4096 16B chunks / 256 thr = 16

    extern __shared__ char dsmem_raw[];
    const uint32_t raw_u32 = smem_u32(dsmem_raw);
    const uint32_t base = (raw_u32 + 1023u) & ~1023u;

    const int tid = threadIdx.x;
    const int wid = tid >> 5;
    const int lane = tid & 31;
    const int warpM = wid & 3;                  // 0..3 -> 32-row slice
    const int warpN = wid >> 2;                 // 0..1 -> 64-col slice
    const int blockRow = blockIdx.y;
    const int blockCol = blockIdx.x;

    const __half* opSrc[2] = { Ah, Bhi };

    auto loadStageAsync = [&](int stage, int k0) {
        #pragma unroll
        for (int i = 0; i < PER_THR; i++) {
            const int idx = tid + 256 * i;
            const int operand = idx >> 11;        // 0..1 (2048 chunks each)
            const int rem = idx & 2047;
            const int row = rem >> 4;             // 0..127
            const int chunk = rem & 15;           // 0..15 (16B units, 256B row)
            const int gRow = (operand == 0 ? blockRow : blockCol) * 128 + row;
            const __half* src = opSrc[operand] + (size_t)gRow * K + k0 + chunk * 8;
            const int csw = (chunk & 8) | ((chunk ^ row) & 7);
            const uint32_t saddr = base + stage * STAGE_B + operand * TILE_B
                                 + row * 256 + (csw << 4);
            cp_async16(saddr, src);
        }
    };

    float acc[2][8][4];                         // [mtile][n8tile][frag]
    #pragma unroll
    for (int m = 0; m < 2; m++)
        #pragma unroll
        for (int n = 0; n < 8; n++)
            #pragma unroll
            for (int j = 0; j < 4; j++) acc[m][n][j] = 0.0f;

    const int nK = K / BK;
    loadStageAsync(0, 0);
    CP_COMMIT();
    if (nK > 1) { loadStageAsync(1, BK); CP_COMMIT(); }

    for (int t = 0; t < nK; t++) {
        if (t + 1 < nK) { CP_WAIT(1); } else { CP_WAIT(0); }
        __syncthreads();   // all threads done with compute(t-1) AND see stage t

        if (t + 2 < nK) { loadStageAsync((t + 2) % NSTAGE, (t + 2) * BK); CP_COMMIT(); }

        const uint32_t sbase = base + (t % NSTAGE) * STAGE_B;
        const uint32_t sA = sbase;
        const uint32_t sB = sbase + TILE_B;

        #pragma unroll
        for (int ks = 0; ks < 8; ks++) {
            const int chunk = ks * 2 + (lane >> 4);   // 0..15

            uint32_t afr[2][4];                 // [mtile][regs]
            #pragma unroll
            for (int mt = 0; mt < 2; mt++) {
                const int row = warpM * 32 + mt * 16 + (lane & 15);
                const int csw = (chunk & 8) | ((chunk ^ row) & 7);
                ldsm_x4(afr[mt], sA + row * 256 + (csw << 4));
            }

            uint32_t bfr[4][4];                 // [npair(16 rows)][regs]
            #pragma unroll
            for (int np = 0; np < 4; np++) {
                const int row = warpN * 64 + np * 16 + (lane & 15);
                const int csw = (chunk & 8) | ((chunk ^ row) & 7);
                ldsm_x4(bfr[np], sB + row * 256 + (csw << 4));
            }

            #pragma unroll
            for (int mt = 0; mt < 2; mt++)
                #pragma unroll
                for (int np = 0; np < 4; np++)
                    #pragma unroll
                    for (int h = 0; h < 2; h++)
                        mma_f16(acc[mt][np * 2 + h], afr[mt],
                                bfr[np][h], bfr[np][h + 2]);
        }
        // next iteration's single barrier protects the ring slot (dist 2 of 3)
    }

    const int g = lane >> 2;
    const int tcol = (lane & 3) * 2;
    #pragma unroll
    for (int mt = 0; mt < 2; mt++) {
        const int r0 = blockRow * 128 + warpM * 32 + mt * 16 + g;
        #pragma unroll
        for (int n = 0; n < 8; n++) {
            const int col = blockCol * 128 + warpN * 64 + n * 8 + tcol;
            float2 v01 = make_float2(acc[mt][n][0], acc[mt][n][1]);
            float2 v23 = make_float2(acc[mt][n][2], acc[mt][n][3]);
            *reinterpret_cast<float2*>(C + (size_t)r0 * N + col) = v01;
            *reinterpret_cast<float2*>(C + (size_t)(r0 + 8) * N + col) = v23;
        }
    }
}

// ---------------------------------------------------------------------------
// Elementwise fp32 -> fp16 round (vectorized).
// ---------------------------------------------------------------------------
__global__ __launch_bounds__(256) void round_f16(
    const float* __restrict__ in, __half* __restrict__ outh, int n4)
{
    const int idx = blockIdx.x * blockDim.x + threadIdx.x;
    if (idx >= n4) return;
    const float4 v = reinterpret_cast<const float4*>(in)[idx];
    __half h[4] = { __float2half(v.x), __float2half(v.y),
                    __float2half(v.z), __float2half(v.w) };
    reinterpret_cast<uint2*>(outh)[idx] = *reinterpret_cast<uint2*>(h);
}

// ---------------------------------------------------------------------------
// Transposed round: W[K,N] fp32 -> Th[N,K] fp16.
// ---------------------------------------------------------------------------
__global__ __launch_bounds__(256) void transpose_h(
    const float* __restrict__ W,
    __half* __restrict__ Th,
    int K, int N)
{
    __shared__ float tile[32][33];
    const int k0 = blockIdx.y * 32;
    const int n0 = blockIdx.x * 32;
    const int tx = threadIdx.x;
    const int ty = threadIdx.y;

    #pragma unroll
    for (int r = ty; r < 32; r += 8)
        tile[r][tx] = W[(size_t)(k0 + r) * N + n0 + tx];
    __syncthreads();

    #pragma unroll
    for (int r = ty; r < 32; r += 8) {
        const float v = tile[tx][r];
        Th[(size_t)(n0 + r) * K + k0 + tx] = __float2half(v);
    }
}

// ---------------------------------------------------------------------------
// Chunked scan, pass 1: per (b, chunk, d) conv + 128-step scan from zero
// state; write the 16 final states to g_cs.
// ---------------------------------------------------------------------------
__global__ __launch_bounds__(256) void scan_pass1(
    const float* __restrict__ conv_w,
    const float* __restrict__ conv_b,
    const float* __restrict__ A_log)
{
    const int gid = blockIdx.x * blockDim.x + threadIdx.x;
    const int d = gid & (DINNER - 1);
    const int rest = gid >> 11;
    const int c = rest & (NCH - 1);
    const int b = rest >> 4;

    const float* xz = g_xz + (size_t)b * LSEQ * (2 * DINNER);
    const int t0 = c * CHUNK;

    const float w0 = conv_w[d * DCONV + 0];
    const float w1 = conv_w[d * DCONV + 1];
    const float w2 = conv_w[d * DCONV + 2];
    const float w3 = conv_w[d * DCONV + 3];
    const float bias = conv_b[d];

    float Aval[DSTATE];
    #pragma unroll
    for (int s = 0; s < DSTATE; s++)
        Aval[s] = -expf(A_log[s * DINNER + d]);

    float st[DSTATE];
    #pragma unroll
    for (int s = 0; s < DSTATE; s++) st[s] = 0.0f;

    float x0 = 0.f, x1 = 0.f, x2 = 0.f, x3 = 0.f;
    if (c > 0) {
        x1 = xz[(size_t)(t0 - 3) * (2 * DINNER) + d];
        x2 = xz[(size_t)(t0 - 2) * (2 * DINNER) + d];
        x3 = xz[(size_t)(t0 - 1) * (2 * DINNER) + d];
    }

    constexpr int U = 8;
    for (int tt = 0; tt < CHUNK; tt += U) {
        float uv[U];
        #pragma unroll
        for (int i = 0; i < U; i++)
            uv[i] = xz[(size_t)(t0 + tt + i) * (2 * DINNER) + d];
        #pragma unroll
        for (int i = 0; i < U; i++) {
            x0 = x1; x1 = x2; x2 = x3; x3 = uv[i];
            float uc = fmaf(w0, x0, fmaf(w1, x1, fmaf(w2, x2, fmaf(w3, x3, bias))));
            #pragma unroll
            for (int s = 0; s < DSTATE; s++)
                st[s] = fmaf(st[s], Aval[s], uc);
        }
    }

    float* cs = g_cs + ((size_t)(b * NCH + c) * DSTATE) * DINNER + d;
    #pragma unroll
    for (int s = 0; s < DSTATE; s++)
        cs[(size_t)s * DINNER] = st[s];
}

// ---------------------------------------------------------------------------
// Chunked scan, pass 2 (combine): init[0]=0; init[c]=A^128*init[c-1]+lf[c-1]
// ---------------------------------------------------------------------------
__global__ __launch_bounds__(256) void scan_combine(
    const float* __restrict__ A_log)
{
    const int gid = blockIdx.x * blockDim.x + threadIdx.x;
    const int d = gid & (DINNER - 1);
    const int b = gid >> 11;

    float A128[DSTATE];
    #pragma unroll
    for (int s = 0; s < DSTATE; s++)
        A128[s] = expf(128.0f * A_log[s * DINNER + d]);

    float init[DSTATE];
    #pragma unroll
    for (int s = 0; s < DSTATE; s++) init[s] = 0.0f;

    for (int c = 0; c < NCH; c++) {
        float* cs = g_cs + ((size_t)(b * NCH + c) * DSTATE) * DINNER + d;
        float lf[DSTATE];
        #pragma unroll
        for (int s = 0; s < DSTATE; s++) lf[s] = cs[(size_t)s * DINNER];
        #pragma unroll
        for (int s = 0; s < DSTATE; s++) cs[(size_t)s * DINNER] = init[s];
        #pragma unroll
        for (int s = 0; s < DSTATE; s++)
            init[s] = fmaf(A128[s], init[s], lf[s]);
    }
}

// ---------------------------------------------------------------------------
// Chunked scan, pass 3: rescan from correct initial state, D skip + silu
// gate, emit y as single fp16.
// ---------------------------------------------------------------------------
__global__ __launch_bounds__(256) void scan_pass2(
    const float* __restrict__ conv_w,
    const float* __restrict__ conv_b,
    const float* __restrict__ A_log,
    const float* __restrict__ D_param)
{
    const int gid = blockIdx.x * blockDim.x + threadIdx.x;
    const int d = gid & (DINNER - 1);
    const int rest = gid >> 11;
    const int c = rest & (NCH - 1);
    const int b = rest >> 4;

    const float* xz = g_xz + (size_t)b * LSEQ * (2 * DINNER);
    __half* yh = g_yh + (size_t)b * LSEQ * DINNER;
    const int t0 = c * CHUNK;

    const float w0 = conv_w[d * DCONV + 0];
    const float w1 = conv_w[d * DCONV + 1];
    const float w2 = conv_w[d * DCONV + 2];
    const float w3 = conv_w[d * DCONV + 3];
    const float bias = conv_b[d];
    const float Dp = D_param[d];

    float Aval[DSTATE];
    #pragma unroll
    for (int s = 0; s < DSTATE; s++)
        Aval[s] = -expf(A_log[s * DINNER + d]);

    float st[DSTATE];
    {
        const float* cs = g_cs + ((size_t)(b * NCH + c) * DSTATE) * DINNER + d;
        #pragma unroll
        for (int s = 0; s < DSTATE; s++) st[s] = cs[(size_t)s * DINNER];
    }

    float x0 = 0.f, x1 = 0.f, x2 = 0.f, x3 = 0.f;
    if (c > 0) {
        x1 = xz[(size_t)(t0 - 3) * (2 * DINNER) + d];
        x2 = xz[(size_t)(t0 - 2) * (2 * DINNER) + d];
        x3 = xz[(size_t)(t0 - 1) * (2 * DINNER) + d];
    }

    constexpr int U = 8;
    for (int tt = 0; tt < CHUNK; tt += U) {
        float uv[U], zv[U];
        #pragma unroll
        for (int i = 0; i < U; i++) {
            const size_t off = (size_t)(t0 + tt + i) * (2 * DINNER) + d;
            uv[i] = xz[off];
            zv[i] = xz[off + DINNER];
        }
        #pragma unroll
        for (int i = 0; i < U; i++) {
            x0 = x1; x1 = x2; x2 = x3; x3 = uv[i];
            float uc = fmaf(w0, x0, fmaf(w1, x1, fmaf(w2, x2, fmaf(w3, x3, bias))));
            float acc = Dp * uc;
            #pragma unroll
            for (int s = 0; s < DSTATE; s++) {
                st[s] = fmaf(st[s], Aval[s], uc);
                acc += st[s];
            }
            const float z = zv[i];
            const float sig = 1.0f / (1.0f + expf(-z));
            yh[(size_t)(t0 + tt + i) * DINNER + d] = __float2half(acc * (z * sig));
        }
    }
}

// ---------------------------------------------------------------------------
extern "C" void kernel_launch(void* const* d_in, const int* in_sizes, int n_in,
                              void* d_out, int out_size)
{
    const float* x       = (const float*)d_in[0];
    const float* W_in    = (const float*)d_in[1];
    const float* conv_w  = (const float*)d_in[2];
    const float* conv_b  = (const float*)d_in[3];
    const float* A_log   = (const float*)d_in[4];
    const float* D_param = (const float*)d_in[5];
    const float* W_out   = (const float*)d_in[6];
    float* out = (float*)d_out;

    float *xz_p;
    __half *xh_p, *winh_p, *wouth_p, *yh_p;
    cudaGetSymbolAddress((void**)&xz_p,    g_xz);
    cudaGetSymbolAddress((void**)&xh_p,    g_xh);
    cudaGetSymbolAddress((void**)&winh_p,  g_WinT_hi);
    cudaGetSymbolAddress((void**)&wouth_p, g_WoutT_hi);
    cudaGetSymbolAddress((void**)&yh_p,    g_yh);

    // 3 stages x 64KB + align pad = 193KB (opt-in; fits 227KB/block limit)
    const int GEMM_SMEM = 3 * 2 * 128 * 256 + 1024;
    cudaFuncSetAttribute(gemm_f16_1p,
                         cudaFuncAttributeMaxDynamicSharedMemorySize, GEMM_SMEM);

    // 1) Round x to fp16
    {
        const int n4 = MTOK * DMODEL / 4;
        round_f16<<<(n4 + 255) / 256, 256>>>(x, xh_p, n4);
    }
    // 2) Transpose weights to fp16 [N,K]
    {
        dim3 blk(32, 8);
        dim3 g1(2 * DINNER / 32, DMODEL / 32);
        transpose_h<<<g1, blk>>>(W_in, winh_p, DMODEL, 2 * DINNER);
        dim3 g2(DMODEL / 32, DINNER / 32);
        transpose_h<<<g2, blk>>>(W_out, wouth_p, DINNER, DMODEL);
    }
    // 3) GEMM1: xz = x @ W_in   (K=1024 -> 8 k-tiles)
    {
        dim3 grid(2 * DINNER / 128, MTOK / 128);
        gemm_f16_1p<<<grid, 256, GEMM_SMEM>>>(MTOK, 2 * DINNER, DMODEL,
                                              xh_p, winh_p, xz_p);
    }
    // 4) Chunked conv+scan+gate (3 passes)
    scan_pass1 <<<(BSZ * NCH * DINNER) / 256, 256>>>(conv_w, conv_b, A_log);
    scan_combine<<<(BSZ * DINNER) / 256, 256>>>(A_log);
    scan_pass2 <<<(BSZ * NCH * DINNER) / 256, 256>>>(conv_w, conv_b, A_log, D_param);
    // 5) GEMM2: out = y @ W_out  (K=2048 -> 16 k-tiles)
    {
        dim3 grid(DMODEL / 128, MTOK / 128);
        gemm_f16_1p<<<grid, 256, GEMM_SMEM>>>(MTOK, DMODEL, DINNER,
                                              yh_p, wouth_p, out);
    }
}